// round 12
// baseline (speedup 1.0000x reference)
#include <cuda_runtime.h>
#include <cstdint>
#include <math.h>

#define SEQ 4096
#define DM  768
#define NH  12
#define HD  64

// Scratch (allocation-free rule: __device__ globals)
__device__ float  g_Q[SEQ * DM];
__device__ float  g_K[SEQ * DM];
__device__ float  g_V[SEQ * DM];
__device__ float  g_AO[SEQ * DM];
__device__ float  g_invf[32];
__device__ float2 g_rope[SEQ * 32];

__device__ __forceinline__ float tf32r(float x) {
    float r; asm("cvt.rna.tf32.f32 %0, %1;" : "=f"(r) : "f"(x)); return r;
}
__device__ __forceinline__ void mma8(float c[4], const uint32_t a[4],
                                     uint32_t b0, uint32_t b1) {
    asm volatile(
        "mma.sync.aligned.m16n8k8.row.col.f32.tf32.tf32.f32 "
        "{%0,%1,%2,%3}, {%4,%5,%6,%7}, {%8,%9}, {%0,%1,%2,%3};"
        : "+f"(c[0]), "+f"(c[1]), "+f"(c[2]), "+f"(c[3])
        : "r"(a[0]), "r"(a[1]), "r"(a[2]), "r"(a[3]), "r"(b0), "r"(b1));
}
__device__ __forceinline__ uint32_t s2u(const void* p) {
    return (uint32_t)__cvta_generic_to_shared(p);
}
#define CPA16(dst, src) \
    asm volatile("cp.async.ca.shared.global [%0], [%1], 16;" :: "r"(dst), "l"(src))
#define CPA_COMMIT() asm volatile("cp.async.commit_group;" ::: "memory")
#define CPA_WAIT0()  asm volatile("cp.async.wait_group 0;" ::: "memory")
#define CPA_WAIT1()  asm volatile("cp.async.wait_group 1;" ::: "memory")

// ---------------------------------------------------------------------------
// RoPE tables
// ---------------------------------------------------------------------------
__global__ void invfreq_kernel() {
    int d = threadIdx.x;   // 32 threads
    g_invf[d] = (float)exp(-(double)(2 * d) / 64.0 * log(10000.0));
}

__global__ __launch_bounds__(256) void rope_table_kernel() {
    int i = blockIdx.x * 256 + threadIdx.x;   // SEQ*32 threads
    int s = i >> 5, d = i & 31;
    float ang = (float)s * g_invf[d];
    float sn, cs;
    sincosf(ang, &sn, &cs);
    g_rope[i] = make_float2(cs, sn);
}

// ---------------------------------------------------------------------------
// TF32 GEMM (mma.sync), cp.async 3-stage smem pipeline + register
// double-buffered fragments (prefetch ks+1 during mma of ks).
// 256 threads, warp tile 64x32. C = A @ W^T; QKV fused (mat = blockIdx.x/6).
// Q output (mat==0) is pre-scaled by 0.125 AFTER tf32 rounding (exact).
// ---------------------------------------------------------------------------
#define GS_FLOATS (128 * 36)
#define GEMM_SMEM (3 * 2 * GS_FLOATS * 4)

template <bool HAS_BIAS>
__global__ __launch_bounds__(256, 2) void gemm_tf32(
    const float* __restrict__ A,
    const float* __restrict__ W0, const float* __restrict__ W1,
    const float* __restrict__ W2,
    const float* __restrict__ bias,
    float* __restrict__ C0, float* __restrict__ C1, float* __restrict__ C2)
{
    extern __shared__ float gsm[];

    const int m0  = blockIdx.y * 128;
    const int nt  = blockIdx.x;
    const int mat = nt / 6;
    const int n0  = (nt % 6) * 128;
    const float* W = (mat == 0) ? W0 : (mat == 1) ? W1 : W2;
    float*       C = (mat == 0) ? C0 : (mat == 1) ? C1 : C2;

    const int t = threadIdx.x, lane = t & 31, wid = t >> 5;
    const int g = lane >> 2, tg = lane & 3;
    const int wm = (wid & 1) * 64, wn = (wid >> 1) * 32;
    const int r_ld = t >> 3, c_ld = (t & 7) << 2;

    float acc[4][4][4] = {};

    auto issue = [&](int slab) {
        float* As = gsm + (slab % 3) * 2 * GS_FLOATS;
        float* Bs = As + GS_FLOATS;
        const int k0 = slab * 32;
#pragma unroll
        for (int it = 0; it < 4; it++) {
            int r = it * 32 + r_ld;
            CPA16(s2u(&As[r * 36 + c_ld]), &A[(size_t)(m0 + r) * DM + k0 + c_ld]);
            CPA16(s2u(&Bs[r * 36 + c_ld]), &W[(size_t)(n0 + r) * DM + k0 + c_ld]);
        }
        CPA_COMMIT();
    };
    issue(0);
    issue(1);

    uint32_t af[2][4][4], bf[2][4][2];
    auto ldfrag = [&](int buf, const float* As, const float* Bs, int ks) {
        const int kb = ks * 8;
#pragma unroll
        for (int mi = 0; mi < 4; mi++) {
            int rb = wm + mi * 16;
            af[buf][mi][0] = __float_as_uint(tf32r(As[(rb + g) * 36 + kb + tg]));
            af[buf][mi][1] = __float_as_uint(tf32r(As[(rb + g + 8) * 36 + kb + tg]));
            af[buf][mi][2] = __float_as_uint(tf32r(As[(rb + g) * 36 + kb + tg + 4]));
            af[buf][mi][3] = __float_as_uint(tf32r(As[(rb + g + 8) * 36 + kb + tg + 4]));
        }
#pragma unroll
        for (int ni = 0; ni < 4; ni++) {
            int cb = wn + ni * 8;
            bf[buf][ni][0] = __float_as_uint(tf32r(Bs[(cb + g) * 36 + kb + tg]));
            bf[buf][ni][1] = __float_as_uint(tf32r(Bs[(cb + g) * 36 + kb + tg + 4]));
        }
    };

    for (int i = 0; i < 24; i++) {
        if (i < 22) CPA_WAIT1(); else CPA_WAIT0();
        __syncthreads();
        if (i + 2 < 24) issue(i + 2);

        const float* As = gsm + (i % 3) * 2 * GS_FLOATS;
        const float* Bs = As + GS_FLOATS;
        ldfrag(0, As, Bs, 0);
#pragma unroll
        for (int ks = 0; ks < 4; ks++) {
            const int cur = ks & 1;
            if (ks < 3) ldfrag(cur ^ 1, As, Bs, ks + 1);
#pragma unroll
            for (int mi = 0; mi < 4; mi++)
#pragma unroll
                for (int ni = 0; ni < 4; ni++)
                    mma8(acc[mi][ni], af[cur][mi], bf[cur][ni][0], bf[cur][ni][1]);
        }
    }

    const float qscl = (mat == 0) ? 0.125f : 1.0f;   // fold score scale into Q
#pragma unroll
    for (int mi = 0; mi < 4; mi++) {
        int r = m0 + wm + mi * 16 + g;
#pragma unroll
        for (int ni = 0; ni < 4; ni++) {
            int c = n0 + wn + ni * 8 + 2 * tg;   // always even
            float v00 = acc[mi][ni][0], v01 = acc[mi][ni][1];
            float v10 = acc[mi][ni][2], v11 = acc[mi][ni][3];
            if (HAS_BIAS) {
                float bx = bias[c], by = bias[c + 1];
                *(float2*)&C[(size_t)r * DM + c] = make_float2(v00 + bx, v01 + by);
                *(float2*)&C[(size_t)(r + 8) * DM + c] = make_float2(v10 + bx, v11 + by);
            } else if (mat < 2) {
                // RoPE: pair (x[2d], x[2d+1]) -> out[d], out[d+32]; tf32-round
                // then exact *0.125 for Q only
                int d = (c & 63) >> 1, hb = c & ~63;
                float2 cs0 = g_rope[r * 32 + d];
                float2 cs1 = g_rope[(r + 8) * 32 + d];
                C[(size_t)r * DM + hb + d]            = tf32r(v00 * cs0.x - v01 * cs0.y) * qscl;
                C[(size_t)r * DM + hb + d + 32]       = tf32r(v00 * cs0.y + v01 * cs0.x) * qscl;
                C[(size_t)(r + 8) * DM + hb + d]      = tf32r(v10 * cs1.x - v11 * cs1.y) * qscl;
                C[(size_t)(r + 8) * DM + hb + d + 32] = tf32r(v10 * cs1.y + v11 * cs1.x) * qscl;
            } else {
                *(float2*)&C[(size_t)r * DM + c] = make_float2(tf32r(v00), tf32r(v01));
                *(float2*)&C[(size_t)(r + 8) * DM + c] = make_float2(tf32r(v10), tf32r(v11));
            }
        }
    }
}

// ---------------------------------------------------------------------------
// Flash attention, tf32 mma.sync, causal. BQ=128, BK=64, 256 threads.
// 3-stage cp.async KV ring; P via quad shuffles (no smem); deferred l.
// Q pre-scaled by 1/8 -> no score multiply. Partial diagonal blocks skip
// fully-masked column tiles (exact: their exp underflows to +0).
// ---------------------------------------------------------------------------
#define KSS 68
#define VSS 72
#define KVSTG 8960                       // floats: 64*68 + 64*72
#define ATT_SMEM (3 * KVSTG * 4)         // 107520 B

__global__ __launch_bounds__(256, 2) void flash_tf32(
    const float* __restrict__ Q, const float* __restrict__ K,
    const float* __restrict__ V, float* __restrict__ O)
{
    extern __shared__ float sm[];
    const int h  = blockIdx.y;
    const int qb = gridDim.x - 1 - blockIdx.x;   // long causal rows first
    const int q0 = qb * 128;
    const int t = threadIdx.x, lane = t & 31, w = t >> 5;
    const int g = lane >> 2, tg = lane & 3;
    const int s1 = (lane & ~3) | (tg >> 1);      // quad-transpose src lanes
    const int s2 = s1 + 2;
    const bool odd = (tg & 1);

    auto issue_kv = [&](int jb, int st) {
        float* Ks = sm + st * KVSTG;
        float* Vs = Ks + 64 * KSS;
        const int k0 = jb * 64;
#pragma unroll
        for (int it = 0; it < 4; it++) {
            int lin = it * 256 + t, r = lin >> 4, c = (lin & 15) << 2;
            CPA16(s2u(&Ks[r * KSS + c]), &K[(size_t)(k0 + r) * DM + h * HD + c]);
            CPA16(s2u(&Vs[r * VSS + c]), &V[(size_t)(k0 + r) * DM + h * HD + c]);
        }
        CPA_COMMIT();
    };

    // groups: [KV0][Q][KV1]
    issue_kv(0, 0);
    {
        float* QB = sm + 2 * KVSTG;
#pragma unroll
        for (int it = 0; it < 8; it++) {
            int lin = it * 256 + t, r = lin >> 4, c = (lin & 15) << 2;
            CPA16(s2u(&QB[r * 68 + c]), &Q[(size_t)(q0 + r) * DM + h * HD + c]);
        }
        CPA_COMMIT();
    }
    issue_kv(1, 1);

    CPA_WAIT1();          // KV0 + Q complete (KV1 may be in flight)
    __syncthreads();

    uint32_t qf[8][4];
    {
        const uint32_t* QB = (const uint32_t*)(sm + 2 * KVSTG);
#pragma unroll
        for (int ks = 0; ks < 8; ks++) {
            int rb = w * 16, kb = ks * 8;
            qf[ks][0] = QB[(rb + g) * 68 + kb + tg];
            qf[ks][1] = QB[(rb + g + 8) * 68 + kb + tg];
            qf[ks][2] = QB[(rb + g) * 68 + kb + tg + 4];
            qf[ks][3] = QB[(rb + g + 8) * 68 + kb + tg + 4];
        }
    }

    float m0r = -1e30f, m1r = -1e30f, l0 = 0.0f, l1 = 0.0f;
    float ao[8][4];
#pragma unroll
    for (int nt = 0; nt < 8; nt++)
#pragma unroll
        for (int c = 0; c < 4; c++) ao[nt][c] = 0.0f;

    const int jbmax = 2 * qb + 1;

    for (int jb = 0; jb <= jbmax; jb++) {
        CPA_WAIT1();          // KV(jb) landed (KV(jb+1) may be in flight)
        __syncthreads();      // visibility + all warps done with stage jb-1
        if (jb + 2 <= jbmax) issue_kv(jb + 2, (jb + 2) % 3);

        const int k0 = jb * 64;
        const int off = k0 - q0;
        // fully-masked warps skip the whole block (exact)
        if (off >= 0 && w * 16 + 15 < off) continue;
        // nt tiles with all columns masked are skipped (their exp == +0)
        const int ntm = (off >= 0) ? min(7, (w * 16 - off + 15) >> 3) : 7;

        const uint32_t* Ks = (const uint32_t*)(sm + (jb % 3) * KVSTG);
        const uint32_t* Vs = Ks + 64 * KSS;

        // S = Q K^T (Q pre-scaled by 1/8)
        float sc[8][4];
#pragma unroll
        for (int nt = 0; nt < 8; nt++)
#pragma unroll
            for (int c = 0; c < 4; c++) sc[nt][c] = 0.0f;

#pragma unroll
        for (int ks = 0; ks < 8; ks++) {
            const int kb = ks * 8;
            for (int nt = 0; nt <= ntm; nt++) {
                uint32_t b0 = Ks[(nt * 8 + g) * KSS + kb + tg];
                uint32_t b1 = Ks[(nt * 8 + g) * KSS + kb + tg + 4];
                mma8(sc[nt], qf[ks], b0, b1);
            }
        }

        // causal mask (scores already scaled)
        if (off >= 0) {
            int lim0 = w * 16 + g - off, lim1 = lim0 + 8;
            for (int nt = 0; nt <= ntm; nt++) {
                int c0 = nt * 8 + 2 * tg, c1 = c0 + 1;
                if (c0 > lim0) sc[nt][0] = -1e9f;
                if (c1 > lim0) sc[nt][1] = -1e9f;
                if (c0 > lim1) sc[nt][2] = -1e9f;
                if (c1 > lim1) sc[nt][3] = -1e9f;
            }
        }

        // online softmax (max reduced now; l deferred to epilogue)
        float mx0 = -1e30f, mx1 = -1e30f;
        for (int nt = 0; nt <= ntm; nt++) {
            mx0 = fmaxf(mx0, fmaxf(sc[nt][0], sc[nt][1]));
            mx1 = fmaxf(mx1, fmaxf(sc[nt][2], sc[nt][3]));
        }
        mx0 = fmaxf(mx0, __shfl_xor_sync(0xffffffffu, mx0, 1));
        mx0 = fmaxf(mx0, __shfl_xor_sync(0xffffffffu, mx0, 2));
        mx1 = fmaxf(mx1, __shfl_xor_sync(0xffffffffu, mx1, 1));
        mx1 = fmaxf(mx1, __shfl_xor_sync(0xffffffffu, mx1, 2));

        float mn0 = fmaxf(m0r, mx0), mn1 = fmaxf(m1r, mx1);
        float al0 = __expf(m0r - mn0), al1 = __expf(m1r - mn1);
        m0r = mn0; m1r = mn1;

        float rs0 = 0.0f, rs1 = 0.0f;
        for (int nt = 0; nt <= ntm; nt++) {
            sc[nt][0] = __expf(sc[nt][0] - mn0);
            sc[nt][1] = __expf(sc[nt][1] - mn0);
            sc[nt][2] = __expf(sc[nt][2] - mn1);
            sc[nt][3] = __expf(sc[nt][3] - mn1);
            rs0 += sc[nt][0] + sc[nt][1];
            rs1 += sc[nt][2] + sc[nt][3];
        }
        l0 = l0 * al0 + rs0;      // per-lane partial; exact (al uniform in quad)
        l1 = l1 * al1 + rs1;
#pragma unroll
        for (int nt = 0; nt < 8; nt++) {
            ao[nt][0] *= al0; ao[nt][1] *= al0;
            ao[nt][2] *= al1; ao[nt][3] *= al1;
        }

        // O += P V : P C-frag -> A-frag via quad shuffles (no smem)
        for (int ks = 0; ks <= ntm; ks++) {
            const int kb = ks * 8;
            float p0 = tf32r(sc[ks][0]), p1 = tf32r(sc[ks][1]);
            float p2 = tf32r(sc[ks][2]), p3 = tf32r(sc[ks][3]);
            float t00 = __shfl_sync(0xffffffffu, p0, s1);
            float t01 = __shfl_sync(0xffffffffu, p1, s1);
            float t10 = __shfl_sync(0xffffffffu, p2, s1);
            float t11 = __shfl_sync(0xffffffffu, p3, s1);
            float t20 = __shfl_sync(0xffffffffu, p0, s2);
            float t21 = __shfl_sync(0xffffffffu, p1, s2);
            float t30 = __shfl_sync(0xffffffffu, p2, s2);
            float t31 = __shfl_sync(0xffffffffu, p3, s2);
            uint32_t pf[4];
            pf[0] = __float_as_uint(odd ? t01 : t00);   // P[g][kb+tg]
            pf[1] = __float_as_uint(odd ? t11 : t10);   // P[g+8][kb+tg]
            pf[2] = __float_as_uint(odd ? t21 : t20);   // P[g][kb+tg+4]
            pf[3] = __float_as_uint(odd ? t31 : t30);   // P[g+8][kb+tg+4]
#pragma unroll
            for (int nt = 0; nt < 8; nt++) {
                uint32_t b0 = Vs[(kb + tg) * VSS + nt * 8 + g];
                uint32_t b1 = Vs[(kb + tg + 4) * VSS + nt * 8 + g];
                mma8(ao[nt], pf, b0, b1);
            }
        }
    }

    // epilogue: reduce deferred l across the 4-lane group, normalize, store
    l0 += __shfl_xor_sync(0xffffffffu, l0, 1);
    l0 += __shfl_xor_sync(0xffffffffu, l0, 2);
    l1 += __shfl_xor_sync(0xffffffffu, l1, 1);
    l1 += __shfl_xor_sync(0xffffffffu, l1, 2);
    float inv0 = 1.0f / l0, inv1 = 1.0f / l1;
    int r0 = q0 + w * 16 + g, r1 = r0 + 8;
#pragma unroll
    for (int nt = 0; nt < 8; nt++) {
        int c = nt * 8 + 2 * tg;
        *(float2*)&O[(size_t)r0 * DM + h * HD + c] =
            make_float2(tf32r(ao[nt][0] * inv0), tf32r(ao[nt][1] * inv0));
        *(float2*)&O[(size_t)r1 * DM + h * HD + c] =
            make_float2(tf32r(ao[nt][2] * inv1), tf32r(ao[nt][3] * inv1));
    }
}

// ---------------------------------------------------------------------------
// Launch
// ---------------------------------------------------------------------------
extern "C" void kernel_launch(void* const* d_in, const int* in_sizes, int n_in,
                              void* d_out, int out_size)
{
    (void)in_sizes; (void)n_in; (void)out_size;
    const float* x  = (const float*)d_in[0];
    const float* Wq = (const float*)d_in[2];
    const float* Wk = (const float*)d_in[3];
    const float* Wv = (const float*)d_in[4];
    const float* Wo = (const float*)d_in[5];
    const float* bo = (const float*)d_in[6];
    float* out = (float*)d_out;

    float *Qp, *Kp, *Vp, *AO;
    cudaGetSymbolAddress((void**)&Qp, g_Q);
    cudaGetSymbolAddress((void**)&Kp, g_K);
    cudaGetSymbolAddress((void**)&Vp, g_V);
    cudaGetSymbolAddress((void**)&AO, g_AO);

    cudaFuncSetAttribute(flash_tf32,
                         cudaFuncAttributeMaxDynamicSharedMemorySize, ATT_SMEM);
    cudaFuncSetAttribute(gemm_tf32<false>,
                         cudaFuncAttributeMaxDynamicSharedMemorySize, GEMM_SMEM);
    cudaFuncSetAttribute(gemm_tf32<true>,
                         cudaFuncAttributeMaxDynamicSharedMemorySize, GEMM_SMEM);

    // RoPE tables (must precede the QKV GEMM epilogue)
    invfreq_kernel<<<1, 32>>>();
    rope_table_kernel<<<(SEQ * 32) / 256, 256>>>();

    // Fused QKV projection + RoPE + tf32 pre-round (+1/8 fold into Q)
    gemm_tf32<false><<<dim3(18, 32), 256, GEMM_SMEM>>>(
        x, Wq, Wk, Wv, nullptr, Qp, Kp, Vp);

    flash_tf32<<<dim3(SEQ / 128, NH), 256, ATT_SMEM>>>(Qp, Kp, Vp, AO);

    // Output projection + bias
    gemm_tf32<true><<<dim3(6, 32), 256, GEMM_SMEM>>>(
        AO, Wo, Wo, Wo, bo, out, out, out);
}

// round 13
// speedup vs baseline: 2.3291x; 2.3291x over previous
#include <cuda_runtime.h>
#include <cstdint>
#include <math.h>

#define SEQ 4096
#define DM  768
#define NH  12
#define HD  64

// Scratch (allocation-free rule: __device__ globals)
__device__ float  g_Q[SEQ * DM];
__device__ float  g_K[SEQ * DM];
__device__ float  g_V[SEQ * DM];
__device__ float  g_AO[SEQ * DM];
__device__ float  g_invf[32];
__device__ float2 g_rope[SEQ * 32];

__device__ __forceinline__ float tf32r(float x) {
    float r; asm("cvt.rna.tf32.f32 %0, %1;" : "=f"(r) : "f"(x)); return r;
}
__device__ __forceinline__ void mma8(float c[4], const uint32_t a[4],
                                     uint32_t b0, uint32_t b1) {
    asm volatile(
        "mma.sync.aligned.m16n8k8.row.col.f32.tf32.tf32.f32 "
        "{%0,%1,%2,%3}, {%4,%5,%6,%7}, {%8,%9}, {%0,%1,%2,%3};"
        : "+f"(c[0]), "+f"(c[1]), "+f"(c[2]), "+f"(c[3])
        : "r"(a[0]), "r"(a[1]), "r"(a[2]), "r"(a[3]), "r"(b0), "r"(b1));
}
__device__ __forceinline__ uint32_t s2u(const void* p) {
    return (uint32_t)__cvta_generic_to_shared(p);
}
#define CPA16(dst, src) \
    asm volatile("cp.async.ca.shared.global [%0], [%1], 16;" :: "r"(dst), "l"(src))
#define CPA_COMMIT() asm volatile("cp.async.commit_group;" ::: "memory")
#define CPA_WAIT0()  asm volatile("cp.async.wait_group 0;" ::: "memory")
#define CPA_WAIT1()  asm volatile("cp.async.wait_group 1;" ::: "memory")

// ---------------------------------------------------------------------------
// RoPE tables
// ---------------------------------------------------------------------------
__global__ void invfreq_kernel() {
    int d = threadIdx.x;   // 32 threads
    g_invf[d] = (float)exp(-(double)(2 * d) / 64.0 * log(10000.0));
}

__global__ __launch_bounds__(256) void rope_table_kernel() {
    int i = blockIdx.x * 256 + threadIdx.x;   // SEQ*32 threads
    int s = i >> 5, d = i & 31;
    float ang = (float)s * g_invf[d];
    float sn, cs;
    sincosf(ang, &sn, &cs);
    g_rope[i] = make_float2(cs, sn);
}

// ---------------------------------------------------------------------------
// TF32 GEMM (mma.sync), cp.async 3-stage pipeline (round-10 proven config).
// 256 threads, warp tile 64x32, in-loop tf32 rounding.
// C = A @ W^T; QKV fused (mat = blockIdx.x/6). 128x128 tile per CTA.
// Q output (mat==0) pre-scaled by 0.125 AFTER tf32 rounding (exact).
// ---------------------------------------------------------------------------
#define GS_FLOATS (128 * 36)
#define GEMM_SMEM (3 * 2 * GS_FLOATS * 4)

template <bool HAS_BIAS>
__global__ __launch_bounds__(256) void gemm_tf32(
    const float* __restrict__ A,
    const float* __restrict__ W0, const float* __restrict__ W1,
    const float* __restrict__ W2,
    const float* __restrict__ bias,
    float* __restrict__ C0, float* __restrict__ C1, float* __restrict__ C2)
{
    extern __shared__ float gsm[];

    const int m0  = blockIdx.y * 128;
    const int nt  = blockIdx.x;
    const int mat = nt / 6;
    const int n0  = (nt % 6) * 128;
    const float* W = (mat == 0) ? W0 : (mat == 1) ? W1 : W2;
    float*       C = (mat == 0) ? C0 : (mat == 1) ? C1 : C2;

    const int t = threadIdx.x, lane = t & 31, wid = t >> 5;
    const int g = lane >> 2, tg = lane & 3;
    const int wm = (wid & 1) * 64, wn = (wid >> 1) * 32;
    const int r_ld = t >> 3, c_ld = (t & 7) << 2;

    float acc[4][4][4] = {};

    auto issue = [&](int slab) {
        float* As = gsm + (slab % 3) * 2 * GS_FLOATS;
        float* Bs = As + GS_FLOATS;
        const int k0 = slab * 32;
#pragma unroll
        for (int it = 0; it < 4; it++) {
            int r = it * 32 + r_ld;
            CPA16(s2u(&As[r * 36 + c_ld]), &A[(size_t)(m0 + r) * DM + k0 + c_ld]);
            CPA16(s2u(&Bs[r * 36 + c_ld]), &W[(size_t)(n0 + r) * DM + k0 + c_ld]);
        }
        CPA_COMMIT();
    };
    issue(0);
    issue(1);

    for (int i = 0; i < 24; i++) {
        if (i < 22) CPA_WAIT1(); else CPA_WAIT0();
        __syncthreads();
        if (i + 2 < 24) issue(i + 2);

        const float* As = gsm + (i % 3) * 2 * GS_FLOATS;
        const float* Bs = As + GS_FLOATS;
#pragma unroll
        for (int ks = 0; ks < 4; ks++) {
            const int kb = ks * 8;
            uint32_t af[4][4], bf[4][2];
#pragma unroll
            for (int mi = 0; mi < 4; mi++) {
                int rb = wm + mi * 16;
                af[mi][0] = __float_as_uint(tf32r(As[(rb + g) * 36 + kb + tg]));
                af[mi][1] = __float_as_uint(tf32r(As[(rb + g + 8) * 36 + kb + tg]));
                af[mi][2] = __float_as_uint(tf32r(As[(rb + g) * 36 + kb + tg + 4]));
                af[mi][3] = __float_as_uint(tf32r(As[(rb + g + 8) * 36 + kb + tg + 4]));
            }
#pragma unroll
            for (int ni = 0; ni < 4; ni++) {
                int cb = wn + ni * 8;
                bf[ni][0] = __float_as_uint(tf32r(Bs[(cb + g) * 36 + kb + tg]));
                bf[ni][1] = __float_as_uint(tf32r(Bs[(cb + g) * 36 + kb + tg + 4]));
            }
#pragma unroll
            for (int mi = 0; mi < 4; mi++)
#pragma unroll
                for (int ni = 0; ni < 4; ni++)
                    mma8(acc[mi][ni], af[mi], bf[ni][0], bf[ni][1]);
        }
    }

    const float qscl = (mat == 0) ? 0.125f : 1.0f;   // fold score scale into Q
#pragma unroll
    for (int mi = 0; mi < 4; mi++) {
        int r = m0 + wm + mi * 16 + g;
#pragma unroll
        for (int ni = 0; ni < 4; ni++) {
            int c = n0 + wn + ni * 8 + 2 * tg;   // always even
            float v00 = acc[mi][ni][0], v01 = acc[mi][ni][1];
            float v10 = acc[mi][ni][2], v11 = acc[mi][ni][3];
            if (HAS_BIAS) {
                float bx = bias[c], by = bias[c + 1];
                *(float2*)&C[(size_t)r * DM + c] = make_float2(v00 + bx, v01 + by);
                *(float2*)&C[(size_t)(r + 8) * DM + c] = make_float2(v10 + bx, v11 + by);
            } else if (mat < 2) {
                // RoPE: pair (x[2d], x[2d+1]) -> out[d], out[d+32]; tf32-round
                // then exact *0.125 for Q only
                int d = (c & 63) >> 1, hb = c & ~63;
                float2 cs0 = g_rope[r * 32 + d];
                float2 cs1 = g_rope[(r + 8) * 32 + d];
                C[(size_t)r * DM + hb + d]            = tf32r(v00 * cs0.x - v01 * cs0.y) * qscl;
                C[(size_t)r * DM + hb + d + 32]       = tf32r(v00 * cs0.y + v01 * cs0.x) * qscl;
                C[(size_t)(r + 8) * DM + hb + d]      = tf32r(v10 * cs1.x - v11 * cs1.y) * qscl;
                C[(size_t)(r + 8) * DM + hb + d + 32] = tf32r(v10 * cs1.y + v11 * cs1.x) * qscl;
            } else {
                *(float2*)&C[(size_t)r * DM + c] = make_float2(tf32r(v00), tf32r(v01));
                *(float2*)&C[(size_t)(r + 8) * DM + c] = make_float2(tf32r(v10), tf32r(v11));
            }
        }
    }
}

// ---------------------------------------------------------------------------
// Flash attention, tf32 mma.sync, causal. BQ=128, BK=64, 256 threads.
// 3-stage cp.async KV ring; P via quad shuffles (no smem); deferred l.
// Q pre-scaled by 1/8. Diagonal tile skip via UNROLLED loops with
// warp-uniform guards (all register-array subscripts compile-time const).
// ---------------------------------------------------------------------------
#define KSS 68
#define VSS 72
#define KVSTG 8960                       // floats: 64*68 + 64*72
#define ATT_SMEM (3 * KVSTG * 4)         // 107520 B

__global__ __launch_bounds__(256, 2) void flash_tf32(
    const float* __restrict__ Q, const float* __restrict__ K,
    const float* __restrict__ V, float* __restrict__ O)
{
    extern __shared__ float sm[];
    const int h  = blockIdx.y;
    const int qb = gridDim.x - 1 - blockIdx.x;   // long causal rows first
    const int q0 = qb * 128;
    const int t = threadIdx.x, lane = t & 31, w = t >> 5;
    const int g = lane >> 2, tg = lane & 3;
    const int s1 = (lane & ~3) | (tg >> 1);      // quad-transpose src lanes
    const int s2 = s1 + 2;
    const bool odd = (tg & 1);

    auto issue_kv = [&](int jb, int st) {
        float* Ks = sm + st * KVSTG;
        float* Vs = Ks + 64 * KSS;
        const int k0 = jb * 64;
#pragma unroll
        for (int it = 0; it < 4; it++) {
            int lin = it * 256 + t, r = lin >> 4, c = (lin & 15) << 2;
            CPA16(s2u(&Ks[r * KSS + c]), &K[(size_t)(k0 + r) * DM + h * HD + c]);
            CPA16(s2u(&Vs[r * VSS + c]), &V[(size_t)(k0 + r) * DM + h * HD + c]);
        }
        CPA_COMMIT();
    };

    // groups: [KV0][Q][KV1]
    issue_kv(0, 0);
    {
        float* QB = sm + 2 * KVSTG;
#pragma unroll
        for (int it = 0; it < 8; it++) {
            int lin = it * 256 + t, r = lin >> 4, c = (lin & 15) << 2;
            CPA16(s2u(&QB[r * 68 + c]), &Q[(size_t)(q0 + r) * DM + h * HD + c]);
        }
        CPA_COMMIT();
    }
    issue_kv(1, 1);

    CPA_WAIT1();          // KV0 + Q complete (KV1 may be in flight)
    __syncthreads();

    uint32_t qf[8][4];
    {
        const uint32_t* QB = (const uint32_t*)(sm + 2 * KVSTG);
#pragma unroll
        for (int ks = 0; ks < 8; ks++) {
            int rb = w * 16, kb = ks * 8;
            qf[ks][0] = QB[(rb + g) * 68 + kb + tg];
            qf[ks][1] = QB[(rb + g + 8) * 68 + kb + tg];
            qf[ks][2] = QB[(rb + g) * 68 + kb + tg + 4];
            qf[ks][3] = QB[(rb + g + 8) * 68 + kb + tg + 4];
        }
    }

    float m0r = -1e30f, m1r = -1e30f, l0 = 0.0f, l1 = 0.0f;
    float ao[8][4];
#pragma unroll
    for (int nt = 0; nt < 8; nt++)
#pragma unroll
        for (int c = 0; c < 4; c++) ao[nt][c] = 0.0f;

    const int jbmax = 2 * qb + 1;

    for (int jb = 0; jb <= jbmax; jb++) {
        CPA_WAIT1();          // KV(jb) landed (KV(jb+1) may be in flight)
        __syncthreads();      // visibility + all warps done with stage jb-1
        if (jb + 2 <= jbmax) issue_kv(jb + 2, (jb + 2) % 3);

        const int k0 = jb * 64;
        const int off = k0 - q0;
        // fully-masked warps skip the whole block (exact)
        if (off >= 0 && w * 16 + 15 < off) continue;
        // tiles nt > ntm are fully masked -> exp == +0 -> exact skip
        // (warp-uniform; used only in guards inside unrolled loops)
        const int ntm = (off >= 0) ? ((w * 16 - off + 15) >> 3) : 7;

        const uint32_t* Ks = (const uint32_t*)(sm + (jb % 3) * KVSTG);
        const uint32_t* Vs = Ks + 64 * KSS;

        // S = Q K^T (Q pre-scaled by 1/8)
        float sc[8][4];
#pragma unroll
        for (int nt = 0; nt < 8; nt++)
#pragma unroll
            for (int c = 0; c < 4; c++) sc[nt][c] = 0.0f;

#pragma unroll
        for (int ks = 0; ks < 8; ks++) {
            const int kb = ks * 8;
#pragma unroll
            for (int nt = 0; nt < 8; nt++) {
                if (nt <= ntm) {
                    uint32_t b0 = Ks[(nt * 8 + g) * KSS + kb + tg];
                    uint32_t b1 = Ks[(nt * 8 + g) * KSS + kb + tg + 4];
                    mma8(sc[nt], qf[ks], b0, b1);
                }
            }
        }

        // causal mask (scores already scaled)
        if (off >= 0) {
            int lim0 = w * 16 + g - off, lim1 = lim0 + 8;
#pragma unroll
            for (int nt = 0; nt < 8; nt++) {
                if (nt <= ntm) {
                    int c0 = nt * 8 + 2 * tg, c1 = c0 + 1;
                    if (c0 > lim0) sc[nt][0] = -1e9f;
                    if (c1 > lim0) sc[nt][1] = -1e9f;
                    if (c0 > lim1) sc[nt][2] = -1e9f;
                    if (c1 > lim1) sc[nt][3] = -1e9f;
                }
            }
        }

        // online softmax (max reduced now; l deferred to epilogue)
        float mx0 = -1e30f, mx1 = -1e30f;
#pragma unroll
        for (int nt = 0; nt < 8; nt++) {
            if (nt <= ntm) {
                mx0 = fmaxf(mx0, fmaxf(sc[nt][0], sc[nt][1]));
                mx1 = fmaxf(mx1, fmaxf(sc[nt][2], sc[nt][3]));
            }
        }
        mx0 = fmaxf(mx0, __shfl_xor_sync(0xffffffffu, mx0, 1));
        mx0 = fmaxf(mx0, __shfl_xor_sync(0xffffffffu, mx0, 2));
        mx1 = fmaxf(mx1, __shfl_xor_sync(0xffffffffu, mx1, 1));
        mx1 = fmaxf(mx1, __shfl_xor_sync(0xffffffffu, mx1, 2));

        float mn0 = fmaxf(m0r, mx0), mn1 = fmaxf(m1r, mx1);
        float al0 = __expf(m0r - mn0), al1 = __expf(m1r - mn1);
        m0r = mn0; m1r = mn1;

        float rs0 = 0.0f, rs1 = 0.0f;
#pragma unroll
        for (int nt = 0; nt < 8; nt++) {
            if (nt <= ntm) {
                sc[nt][0] = __expf(sc[nt][0] - mn0);
                sc[nt][1] = __expf(sc[nt][1] - mn0);
                sc[nt][2] = __expf(sc[nt][2] - mn1);
                sc[nt][3] = __expf(sc[nt][3] - mn1);
                rs0 += sc[nt][0] + sc[nt][1];
                rs1 += sc[nt][2] + sc[nt][3];
            }
        }
        l0 = l0 * al0 + rs0;      // per-lane partial; exact (al uniform in quad)
        l1 = l1 * al1 + rs1;
#pragma unroll
        for (int nt = 0; nt < 8; nt++) {
            ao[nt][0] *= al0; ao[nt][1] *= al0;
            ao[nt][2] *= al1; ao[nt][3] *= al1;
        }

        // O += P V : P C-frag -> A-frag via quad shuffles (no smem)
#pragma unroll
        for (int ks = 0; ks < 8; ks++) {
            if (ks <= ntm) {
                const int kb = ks * 8;
                float p0 = tf32r(sc[ks][0]), p1 = tf32r(sc[ks][1]);
                float p2 = tf32r(sc[ks][2]), p3 = tf32r(sc[ks][3]);
                float t00 = __shfl_sync(0xffffffffu, p0, s1);
                float t01 = __shfl_sync(0xffffffffu, p1, s1);
                float t10 = __shfl_sync(0xffffffffu, p2, s1);
                float t11 = __shfl_sync(0xffffffffu, p3, s1);
                float t20 = __shfl_sync(0xffffffffu, p0, s2);
                float t21 = __shfl_sync(0xffffffffu, p1, s2);
                float t30 = __shfl_sync(0xffffffffu, p2, s2);
                float t31 = __shfl_sync(0xffffffffu, p3, s2);
                uint32_t pf[4];
                pf[0] = __float_as_uint(odd ? t01 : t00);   // P[g][kb+tg]
                pf[1] = __float_as_uint(odd ? t11 : t10);   // P[g+8][kb+tg]
                pf[2] = __float_as_uint(odd ? t21 : t20);   // P[g][kb+tg+4]
                pf[3] = __float_as_uint(odd ? t31 : t30);   // P[g+8][kb+tg+4]
#pragma unroll
                for (int nt = 0; nt < 8; nt++) {
                    uint32_t b0 = Vs[(kb + tg) * VSS + nt * 8 + g];
                    uint32_t b1 = Vs[(kb + tg + 4) * VSS + nt * 8 + g];
                    mma8(ao[nt], pf, b0, b1);
                }
            }
        }
    }

    // epilogue: reduce deferred l across the 4-lane group, normalize, store
    l0 += __shfl_xor_sync(0xffffffffu, l0, 1);
    l0 += __shfl_xor_sync(0xffffffffu, l0, 2);
    l1 += __shfl_xor_sync(0xffffffffu, l1, 1);
    l1 += __shfl_xor_sync(0xffffffffu, l1, 2);
    float inv0 = 1.0f / l0, inv1 = 1.0f / l1;
    int r0 = q0 + w * 16 + g, r1 = r0 + 8;
#pragma unroll
    for (int nt = 0; nt < 8; nt++) {
        int c = nt * 8 + 2 * tg;
        *(float2*)&O[(size_t)r0 * DM + h * HD + c] =
            make_float2(tf32r(ao[nt][0] * inv0), tf32r(ao[nt][1] * inv0));
        *(float2*)&O[(size_t)r1 * DM + h * HD + c] =
            make_float2(tf32r(ao[nt][2] * inv1), tf32r(ao[nt][3] * inv1));
    }
}

// ---------------------------------------------------------------------------
// Launch
// ---------------------------------------------------------------------------
extern "C" void kernel_launch(void* const* d_in, const int* in_sizes, int n_in,
                              void* d_out, int out_size)
{
    (void)in_sizes; (void)n_in; (void)out_size;
    const float* x  = (const float*)d_in[0];
    const float* Wq = (const float*)d_in[2];
    const float* Wk = (const float*)d_in[3];
    const float* Wv = (const float*)d_in[4];
    const float* Wo = (const float*)d_in[5];
    const float* bo = (const float*)d_in[6];
    float* out = (float*)d_out;

    float *Qp, *Kp, *Vp, *AO;
    cudaGetSymbolAddress((void**)&Qp, g_Q);
    cudaGetSymbolAddress((void**)&Kp, g_K);
    cudaGetSymbolAddress((void**)&Vp, g_V);
    cudaGetSymbolAddress((void**)&AO, g_AO);

    cudaFuncSetAttribute(flash_tf32,
                         cudaFuncAttributeMaxDynamicSharedMemorySize, ATT_SMEM);
    cudaFuncSetAttribute(gemm_tf32<false>,
                         cudaFuncAttributeMaxDynamicSharedMemorySize, GEMM_SMEM);
    cudaFuncSetAttribute(gemm_tf32<true>,
                         cudaFuncAttributeMaxDynamicSharedMemorySize, GEMM_SMEM);

    // RoPE tables (must precede the QKV GEMM epilogue)
    invfreq_kernel<<<1, 32>>>();
    rope_table_kernel<<<(SEQ * 32) / 256, 256>>>();

    // Fused QKV projection + RoPE + tf32 pre-round (+1/8 fold into Q)
    gemm_tf32<false><<<dim3(18, 32), 256, GEMM_SMEM>>>(
        x, Wq, Wk, Wv, nullptr, Qp, Kp, Vp);

    flash_tf32<<<dim3(SEQ / 128, NH), 256, ATT_SMEM>>>(Qp, Kp, Vp, AO);

    // Output projection + bias
    gemm_tf32<true><<<dim3(6, 32), 256, GEMM_SMEM>>>(
        AO, Wo, Wo, Wo, bo, out, out, out);
}

// round 14
// speedup vs baseline: 2.4540x; 1.0536x over previous
#include <cuda_runtime.h>
#include <cstdint>
#include <math.h>

#define SEQ 4096
#define DM  768
#define NH  12
#define HD  64

// Scratch (allocation-free rule: __device__ globals)
__device__ float  g_Q[SEQ * DM];
__device__ float  g_K[SEQ * DM];
__device__ float  g_V[SEQ * DM];
__device__ float  g_AO[SEQ * DM];
__device__ float  g_invf[32];
__device__ float2 g_rope[SEQ * 32];

__device__ __forceinline__ float tf32r(float x) {
    float r; asm("cvt.rna.tf32.f32 %0, %1;" : "=f"(r) : "f"(x)); return r;
}
__device__ __forceinline__ void mma8(float c[4], const uint32_t a[4],
                                     uint32_t b0, uint32_t b1) {
    asm volatile(
        "mma.sync.aligned.m16n8k8.row.col.f32.tf32.tf32.f32 "
        "{%0,%1,%2,%3}, {%4,%5,%6,%7}, {%8,%9}, {%0,%1,%2,%3};"
        : "+f"(c[0]), "+f"(c[1]), "+f"(c[2]), "+f"(c[3])
        : "r"(a[0]), "r"(a[1]), "r"(a[2]), "r"(a[3]), "r"(b0), "r"(b1));
}
__device__ __forceinline__ uint32_t s2u(const void* p) {
    return (uint32_t)__cvta_generic_to_shared(p);
}
#define CPA16(dst, src) \
    asm volatile("cp.async.ca.shared.global [%0], [%1], 16;" :: "r"(dst), "l"(src))
#define CPA_COMMIT() asm volatile("cp.async.commit_group;" ::: "memory")
#define CPA_WAIT0()  asm volatile("cp.async.wait_group 0;" ::: "memory")
#define CPA_WAIT1()  asm volatile("cp.async.wait_group 1;" ::: "memory")

// ---------------------------------------------------------------------------
// RoPE tables
// ---------------------------------------------------------------------------
__global__ void invfreq_kernel() {
    int d = threadIdx.x;   // 32 threads
    g_invf[d] = (float)exp(-(double)(2 * d) / 64.0 * log(10000.0));
}

__global__ __launch_bounds__(256) void rope_table_kernel() {
    int i = blockIdx.x * 256 + threadIdx.x;   // SEQ*32 threads
    int s = i >> 5, d = i & 31;
    float ang = (float)s * g_invf[d];
    float sn, cs;
    sincosf(ang, &sn, &cs);
    g_rope[i] = make_float2(cs, sn);
}

// ---------------------------------------------------------------------------
// TF32 GEMM (mma.sync), cp.async 3-stage pipeline (round-10 proven config).
// 256 threads, warp tile 64x32, in-loop tf32 rounding.
// C = A @ W^T; QKV fused (mat = blockIdx.x/6). 128x128 tile per CTA.
// Q output (mat==0) pre-scaled by 0.125 AFTER tf32 rounding (exact).
// ---------------------------------------------------------------------------
#define GS_FLOATS (128 * 36)
#define GEMM_SMEM (3 * 2 * GS_FLOATS * 4)

template <bool HAS_BIAS>
__global__ __launch_bounds__(256) void gemm_tf32(
    const float* __restrict__ A,
    const float* __restrict__ W0, const float* __restrict__ W1,
    const float* __restrict__ W2,
    const float* __restrict__ bias,
    float* __restrict__ C0, float* __restrict__ C1, float* __restrict__ C2)
{
    extern __shared__ float gsm[];

    const int m0  = blockIdx.y * 128;
    const int nt  = blockIdx.x;
    const int mat = nt / 6;
    const int n0  = (nt % 6) * 128;
    const float* W = (mat == 0) ? W0 : (mat == 1) ? W1 : W2;
    float*       C = (mat == 0) ? C0 : (mat == 1) ? C1 : C2;

    const int t = threadIdx.x, lane = t & 31, wid = t >> 5;
    const int g = lane >> 2, tg = lane & 3;
    const int wm = (wid & 1) * 64, wn = (wid >> 1) * 32;
    const int r_ld = t >> 3, c_ld = (t & 7) << 2;

    float acc[4][4][4] = {};

    auto issue = [&](int slab) {
        float* As = gsm + (slab % 3) * 2 * GS_FLOATS;
        float* Bs = As + GS_FLOATS;
        const int k0 = slab * 32;
#pragma unroll
        for (int it = 0; it < 4; it++) {
            int r = it * 32 + r_ld;
            CPA16(s2u(&As[r * 36 + c_ld]), &A[(size_t)(m0 + r) * DM + k0 + c_ld]);
            CPA16(s2u(&Bs[r * 36 + c_ld]), &W[(size_t)(n0 + r) * DM + k0 + c_ld]);
        }
        CPA_COMMIT();
    };
    issue(0);
    issue(1);

    for (int i = 0; i < 24; i++) {
        if (i < 22) CPA_WAIT1(); else CPA_WAIT0();
        __syncthreads();
        if (i + 2 < 24) issue(i + 2);

        const float* As = gsm + (i % 3) * 2 * GS_FLOATS;
        const float* Bs = As + GS_FLOATS;
#pragma unroll
        for (int ks = 0; ks < 4; ks++) {
            const int kb = ks * 8;
            uint32_t af[4][4], bf[4][2];
#pragma unroll
            for (int mi = 0; mi < 4; mi++) {
                int rb = wm + mi * 16;
                af[mi][0] = __float_as_uint(tf32r(As[(rb + g) * 36 + kb + tg]));
                af[mi][1] = __float_as_uint(tf32r(As[(rb + g + 8) * 36 + kb + tg]));
                af[mi][2] = __float_as_uint(tf32r(As[(rb + g) * 36 + kb + tg + 4]));
                af[mi][3] = __float_as_uint(tf32r(As[(rb + g + 8) * 36 + kb + tg + 4]));
            }
#pragma unroll
            for (int ni = 0; ni < 4; ni++) {
                int cb = wn + ni * 8;
                bf[ni][0] = __float_as_uint(tf32r(Bs[(cb + g) * 36 + kb + tg]));
                bf[ni][1] = __float_as_uint(tf32r(Bs[(cb + g) * 36 + kb + tg + 4]));
            }
#pragma unroll
            for (int mi = 0; mi < 4; mi++)
#pragma unroll
                for (int ni = 0; ni < 4; ni++)
                    mma8(acc[mi][ni], af[mi], bf[ni][0], bf[ni][1]);
        }
    }

    const float qscl = (mat == 0) ? 0.125f : 1.0f;   // fold score scale into Q
#pragma unroll
    for (int mi = 0; mi < 4; mi++) {
        int r = m0 + wm + mi * 16 + g;
#pragma unroll
        for (int ni = 0; ni < 4; ni++) {
            int c = n0 + wn + ni * 8 + 2 * tg;   // always even
            float v00 = acc[mi][ni][0], v01 = acc[mi][ni][1];
            float v10 = acc[mi][ni][2], v11 = acc[mi][ni][3];
            if (HAS_BIAS) {
                float bx = bias[c], by = bias[c + 1];
                *(float2*)&C[(size_t)r * DM + c] = make_float2(v00 + bx, v01 + by);
                *(float2*)&C[(size_t)(r + 8) * DM + c] = make_float2(v10 + bx, v11 + by);
            } else if (mat < 2) {
                // RoPE: pair (x[2d], x[2d+1]) -> out[d], out[d+32]; tf32-round
                // then exact *0.125 for Q only
                int d = (c & 63) >> 1, hb = c & ~63;
                float2 cs0 = g_rope[r * 32 + d];
                float2 cs1 = g_rope[(r + 8) * 32 + d];
                C[(size_t)r * DM + hb + d]            = tf32r(v00 * cs0.x - v01 * cs0.y) * qscl;
                C[(size_t)r * DM + hb + d + 32]       = tf32r(v00 * cs0.y + v01 * cs0.x) * qscl;
                C[(size_t)(r + 8) * DM + hb + d]      = tf32r(v10 * cs1.x - v11 * cs1.y) * qscl;
                C[(size_t)(r + 8) * DM + hb + d + 32] = tf32r(v10 * cs1.y + v11 * cs1.x) * qscl;
            } else {
                *(float2*)&C[(size_t)r * DM + c] = make_float2(tf32r(v00), tf32r(v01));
                *(float2*)&C[(size_t)(r + 8) * DM + c] = make_float2(tf32r(v10), tf32r(v11));
            }
        }
    }
}

// ---------------------------------------------------------------------------
// Flash attention, tf32 mma.sync, causal. BQ=128, BK=64, 256 threads.
// EXACT round-10 structure (measured 271.6us) with score-scale multiplies
// removed (Q pre-scaled by 1/8 in GEMM epilogue; bit-exact).
// 3-stage cp.async KV ring; P via quad shuffles (no smem); deferred l.
// ---------------------------------------------------------------------------
#define KSS 68
#define VSS 72
#define KVSTG 8960                       // floats: 64*68 + 64*72
#define ATT_SMEM (3 * KVSTG * 4)         // 107520 B

__global__ __launch_bounds__(256, 2) void flash_tf32(
    const float* __restrict__ Q, const float* __restrict__ K,
    const float* __restrict__ V, float* __restrict__ O)
{
    extern __shared__ float sm[];
    const int h  = blockIdx.y;
    const int qb = gridDim.x - 1 - blockIdx.x;   // long causal rows first
    const int q0 = qb * 128;
    const int t = threadIdx.x, lane = t & 31, w = t >> 5;
    const int g = lane >> 2, tg = lane & 3;
    const int s1 = (lane & ~3) | (tg >> 1);      // quad-transpose src lanes
    const int s2 = s1 + 2;
    const bool odd = (tg & 1);

    auto issue_kv = [&](int jb, int st) {
        float* Ks = sm + st * KVSTG;
        float* Vs = Ks + 64 * KSS;
        const int k0 = jb * 64;
#pragma unroll
        for (int it = 0; it < 4; it++) {
            int lin = it * 256 + t, r = lin >> 4, c = (lin & 15) << 2;
            CPA16(s2u(&Ks[r * KSS + c]), &K[(size_t)(k0 + r) * DM + h * HD + c]);
            CPA16(s2u(&Vs[r * VSS + c]), &V[(size_t)(k0 + r) * DM + h * HD + c]);
        }
        CPA_COMMIT();
    };

    // groups: [KV0][Q][KV1]
    issue_kv(0, 0);
    {
        float* QB = sm + 2 * KVSTG;
#pragma unroll
        for (int it = 0; it < 8; it++) {
            int lin = it * 256 + t, r = lin >> 4, c = (lin & 15) << 2;
            CPA16(s2u(&QB[r * 68 + c]), &Q[(size_t)(q0 + r) * DM + h * HD + c]);
        }
        CPA_COMMIT();
    }
    issue_kv(1, 1);

    CPA_WAIT1();          // KV0 + Q complete (KV1 may be in flight)
    __syncthreads();

    uint32_t qf[8][4];
    {
        const uint32_t* QB = (const uint32_t*)(sm + 2 * KVSTG);
#pragma unroll
        for (int ks = 0; ks < 8; ks++) {
            int rb = w * 16, kb = ks * 8;
            qf[ks][0] = QB[(rb + g) * 68 + kb + tg];
            qf[ks][1] = QB[(rb + g + 8) * 68 + kb + tg];
            qf[ks][2] = QB[(rb + g) * 68 + kb + tg + 4];
            qf[ks][3] = QB[(rb + g + 8) * 68 + kb + tg + 4];
        }
    }

    float m0r = -1e30f, m1r = -1e30f, l0 = 0.0f, l1 = 0.0f;
    float ao[8][4];
#pragma unroll
    for (int nt = 0; nt < 8; nt++)
#pragma unroll
        for (int c = 0; c < 4; c++) ao[nt][c] = 0.0f;

    const int jbmax = 2 * qb + 1;

    for (int jb = 0; jb <= jbmax; jb++) {
        CPA_WAIT1();          // KV(jb) landed (KV(jb+1) may be in flight)
        __syncthreads();      // visibility + all warps done with stage jb-1
        if (jb + 2 <= jbmax) issue_kv(jb + 2, (jb + 2) % 3);

        const int k0 = jb * 64;
        const int off = k0 - q0;
        // off==64: warps 0-3 (rows < 64) fully masked -> exact skip
        if (off == 64 && w < 4) continue;

        const uint32_t* Ks = (const uint32_t*)(sm + (jb % 3) * KVSTG);
        const uint32_t* Vs = Ks + 64 * KSS;

        // S = Q K^T (Q pre-scaled by 1/8 -> no score multiply anywhere)
        float sc[8][4];
#pragma unroll
        for (int nt = 0; nt < 8; nt++)
#pragma unroll
            for (int c = 0; c < 4; c++) sc[nt][c] = 0.0f;

#pragma unroll
        for (int ks = 0; ks < 8; ks++) {
            const int kb = ks * 8;
#pragma unroll
            for (int nt = 0; nt < 8; nt++) {
                uint32_t b0 = Ks[(nt * 8 + g) * KSS + kb + tg];
                uint32_t b1 = Ks[(nt * 8 + g) * KSS + kb + tg + 4];
                mma8(sc[nt], qf[ks], b0, b1);
            }
        }

        // causal mask (diagonal blocks only)
        if (off >= 0) {
            int lim0 = w * 16 + g - off, lim1 = lim0 + 8;
#pragma unroll
            for (int nt = 0; nt < 8; nt++) {
                int c0 = nt * 8 + 2 * tg, c1 = c0 + 1;
                sc[nt][0] = (c0 <= lim0) ? sc[nt][0] : -1e9f;
                sc[nt][1] = (c1 <= lim0) ? sc[nt][1] : -1e9f;
                sc[nt][2] = (c0 <= lim1) ? sc[nt][2] : -1e9f;
                sc[nt][3] = (c1 <= lim1) ? sc[nt][3] : -1e9f;
            }
        }

        // online softmax (max reduced now; l deferred to epilogue)
        float mx0 = -1e30f, mx1 = -1e30f;
#pragma unroll
        for (int nt = 0; nt < 8; nt++) {
            mx0 = fmaxf(mx0, fmaxf(sc[nt][0], sc[nt][1]));
            mx1 = fmaxf(mx1, fmaxf(sc[nt][2], sc[nt][3]));
        }
        mx0 = fmaxf(mx0, __shfl_xor_sync(0xffffffffu, mx0, 1));
        mx0 = fmaxf(mx0, __shfl_xor_sync(0xffffffffu, mx0, 2));
        mx1 = fmaxf(mx1, __shfl_xor_sync(0xffffffffu, mx1, 1));
        mx1 = fmaxf(mx1, __shfl_xor_sync(0xffffffffu, mx1, 2));

        float mn0 = fmaxf(m0r, mx0), mn1 = fmaxf(m1r, mx1);
        float al0 = __expf(m0r - mn0), al1 = __expf(m1r - mn1);
        m0r = mn0; m1r = mn1;

        float rs0 = 0.0f, rs1 = 0.0f;
#pragma unroll
        for (int nt = 0; nt < 8; nt++) {
            sc[nt][0] = __expf(sc[nt][0] - mn0);
            sc[nt][1] = __expf(sc[nt][1] - mn0);
            sc[nt][2] = __expf(sc[nt][2] - mn1);
            sc[nt][3] = __expf(sc[nt][3] - mn1);
            rs0 += sc[nt][0] + sc[nt][1];
            rs1 += sc[nt][2] + sc[nt][3];
        }
        l0 = l0 * al0 + rs0;      // per-lane partial; exact (al uniform in quad)
        l1 = l1 * al1 + rs1;
#pragma unroll
        for (int nt = 0; nt < 8; nt++) {
            ao[nt][0] *= al0; ao[nt][1] *= al0;
            ao[nt][2] *= al1; ao[nt][3] *= al1;
        }

        // O += P V : P C-frag -> A-frag via quad shuffles (no smem)
#pragma unroll
        for (int ks = 0; ks < 8; ks++) {
            const int kb = ks * 8;
            float p0 = tf32r(sc[ks][0]), p1 = tf32r(sc[ks][1]);
            float p2 = tf32r(sc[ks][2]), p3 = tf32r(sc[ks][3]);
            float t00 = __shfl_sync(0xffffffffu, p0, s1);
            float t01 = __shfl_sync(0xffffffffu, p1, s1);
            float t10 = __shfl_sync(0xffffffffu, p2, s1);
            float t11 = __shfl_sync(0xffffffffu, p3, s1);
            float t20 = __shfl_sync(0xffffffffu, p0, s2);
            float t21 = __shfl_sync(0xffffffffu, p1, s2);
            float t30 = __shfl_sync(0xffffffffu, p2, s2);
            float t31 = __shfl_sync(0xffffffffu, p3, s2);
            uint32_t pf[4];
            pf[0] = __float_as_uint(odd ? t01 : t00);   // P[g][kb+tg]
            pf[1] = __float_as_uint(odd ? t11 : t10);   // P[g+8][kb+tg]
            pf[2] = __float_as_uint(odd ? t21 : t20);   // P[g][kb+tg+4]
            pf[3] = __float_as_uint(odd ? t31 : t30);   // P[g+8][kb+tg+4]
#pragma unroll
            for (int nt = 0; nt < 8; nt++) {
                uint32_t b0 = Vs[(kb + tg) * VSS + nt * 8 + g];
                uint32_t b1 = Vs[(kb + tg + 4) * VSS + nt * 8 + g];
                mma8(ao[nt], pf, b0, b1);
            }
        }
    }

    // epilogue: reduce deferred l across the 4-lane group, normalize, store
    l0 += __shfl_xor_sync(0xffffffffu, l0, 1);
    l0 += __shfl_xor_sync(0xffffffffu, l0, 2);
    l1 += __shfl_xor_sync(0xffffffffu, l1, 1);
    l1 += __shfl_xor_sync(0xffffffffu, l1, 2);
    float inv0 = 1.0f / l0, inv1 = 1.0f / l1;
    int r0 = q0 + w * 16 + g, r1 = r0 + 8;
#pragma unroll
    for (int nt = 0; nt < 8; nt++) {
        int c = nt * 8 + 2 * tg;
        *(float2*)&O[(size_t)r0 * DM + h * HD + c] =
            make_float2(tf32r(ao[nt][0] * inv0), tf32r(ao[nt][1] * inv0));
        *(float2*)&O[(size_t)r1 * DM + h * HD + c] =
            make_float2(tf32r(ao[nt][2] * inv1), tf32r(ao[nt][3] * inv1));
    }
}

// ---------------------------------------------------------------------------
// Launch
// ---------------------------------------------------------------------------
extern "C" void kernel_launch(void* const* d_in, const int* in_sizes, int n_in,
                              void* d_out, int out_size)
{
    (void)in_sizes; (void)n_in; (void)out_size;
    const float* x  = (const float*)d_in[0];
    const float* Wq = (const float*)d_in[2];
    const float* Wk = (const float*)d_in[3];
    const float* Wv = (const float*)d_in[4];
    const float* Wo = (const float*)d_in[5];
    const float* bo = (const float*)d_in[6];
    float* out = (float*)d_out;

    float *Qp, *Kp, *Vp, *AO;
    cudaGetSymbolAddress((void**)&Qp, g_Q);
    cudaGetSymbolAddress((void**)&Kp, g_K);
    cudaGetSymbolAddress((void**)&Vp, g_V);
    cudaGetSymbolAddress((void**)&AO, g_AO);

    cudaFuncSetAttribute(flash_tf32,
                         cudaFuncAttributeMaxDynamicSharedMemorySize, ATT_SMEM);
    cudaFuncSetAttribute(gemm_tf32<false>,
                         cudaFuncAttributeMaxDynamicSharedMemorySize, GEMM_SMEM);
    cudaFuncSetAttribute(gemm_tf32<true>,
                         cudaFuncAttributeMaxDynamicSharedMemorySize, GEMM_SMEM);

    // RoPE tables (must precede the QKV GEMM epilogue)
    invfreq_kernel<<<1, 32>>>();
    rope_table_kernel<<<(SEQ * 32) / 256, 256>>>();

    // Fused QKV projection + RoPE + tf32 pre-round (+1/8 fold into Q)
    gemm_tf32<false><<<dim3(18, 32), 256, GEMM_SMEM>>>(
        x, Wq, Wk, Wv, nullptr, Qp, Kp, Vp);

    flash_tf32<<<dim3(SEQ / 128, NH), 256, ATT_SMEM>>>(Qp, Kp, Vp, AO);

    // Output projection + bias
    gemm_tf32<true><<<dim3(6, 32), 256, GEMM_SMEM>>>(
        AO, Wo, Wo, Wo, bo, out, out, out);
}

// round 15
// speedup vs baseline: 2.5915x; 1.0560x over previous
#include <cuda_runtime.h>
#include <cstdint>
#include <math.h>

#define SEQ 4096
#define DM  768
#define NH  12
#define HD  64

// Scratch (allocation-free rule: __device__ globals)
__device__ float  g_Q[SEQ * DM];
__device__ float  g_K[SEQ * DM];
__device__ float  g_V[SEQ * DM];
__device__ float  g_AO[SEQ * DM];
__device__ float  g_invf[32];
__device__ float2 g_rope[SEQ * 32];

__device__ __forceinline__ float tf32r(float x) {
    float r; asm("cvt.rna.tf32.f32 %0, %1;" : "=f"(r) : "f"(x)); return r;
}
__device__ __forceinline__ void mma8(float c[4], const uint32_t a[4],
                                     uint32_t b0, uint32_t b1) {
    asm volatile(
        "mma.sync.aligned.m16n8k8.row.col.f32.tf32.tf32.f32 "
        "{%0,%1,%2,%3}, {%4,%5,%6,%7}, {%8,%9}, {%0,%1,%2,%3};"
        : "+f"(c[0]), "+f"(c[1]), "+f"(c[2]), "+f"(c[3])
        : "r"(a[0]), "r"(a[1]), "r"(a[2]), "r"(a[3]), "r"(b0), "r"(b1));
}
__device__ __forceinline__ uint32_t s2u(const void* p) {
    return (uint32_t)__cvta_generic_to_shared(p);
}
#define CPA16(dst, src) \
    asm volatile("cp.async.ca.shared.global [%0], [%1], 16;" :: "r"(dst), "l"(src))
#define CPA_COMMIT() asm volatile("cp.async.commit_group;" ::: "memory")
#define CPA_WAIT0()  asm volatile("cp.async.wait_group 0;" ::: "memory")
#define CPA_WAIT1()  asm volatile("cp.async.wait_group 1;" ::: "memory")

// ---------------------------------------------------------------------------
// RoPE tables
// ---------------------------------------------------------------------------
__global__ void invfreq_kernel() {
    int d = threadIdx.x;   // 32 threads
    g_invf[d] = (float)exp(-(double)(2 * d) / 64.0 * log(10000.0));
}

__global__ __launch_bounds__(256) void rope_table_kernel() {
    int i = blockIdx.x * 256 + threadIdx.x;   // SEQ*32 threads
    int s = i >> 5, d = i & 31;
    float ang = (float)s * g_invf[d];
    float sn, cs;
    sincosf(ang, &sn, &cs);
    g_rope[i] = make_float2(cs, sn);
}

// ---------------------------------------------------------------------------
// TF32 GEMM (mma.sync), cp.async 3-stage pipeline.
// 256 threads, warp tile 64x32, in-loop tf32 rounding.
// C = A @ W^T; QKV fused (mat = blockIdx.x/6). 128x128 tile per CTA.
// ---------------------------------------------------------------------------
#define GS_FLOATS (128 * 36)
#define GEMM_SMEM (3 * 2 * GS_FLOATS * 4)

template <bool HAS_BIAS>
__global__ __launch_bounds__(256) void gemm_tf32(
    const float* __restrict__ A,
    const float* __restrict__ W0, const float* __restrict__ W1,
    const float* __restrict__ W2,
    const float* __restrict__ bias,
    float* __restrict__ C0, float* __restrict__ C1, float* __restrict__ C2)
{
    extern __shared__ float gsm[];

    const int m0  = blockIdx.y * 128;
    const int nt  = blockIdx.x;
    const int mat = nt / 6;
    const int n0  = (nt % 6) * 128;
    const float* W = (mat == 0) ? W0 : (mat == 1) ? W1 : W2;
    float*       C = (mat == 0) ? C0 : (mat == 1) ? C1 : C2;

    const int t = threadIdx.x, lane = t & 31, wid = t >> 5;
    const int g = lane >> 2, tg = lane & 3;
    const int wm = (wid & 1) * 64, wn = (wid >> 1) * 32;
    const int r_ld = t >> 3, c_ld = (t & 7) << 2;

    float acc[4][4][4] = {};

    auto issue = [&](int slab) {
        float* As = gsm + (slab % 3) * 2 * GS_FLOATS;
        float* Bs = As + GS_FLOATS;
        const int k0 = slab * 32;
#pragma unroll
        for (int it = 0; it < 4; it++) {
            int r = it * 32 + r_ld;
            CPA16(s2u(&As[r * 36 + c_ld]), &A[(size_t)(m0 + r) * DM + k0 + c_ld]);
            CPA16(s2u(&Bs[r * 36 + c_ld]), &W[(size_t)(n0 + r) * DM + k0 + c_ld]);
        }
        CPA_COMMIT();
    };
    issue(0);
    issue(1);

    for (int i = 0; i < 24; i++) {
        if (i < 22) CPA_WAIT1(); else CPA_WAIT0();
        __syncthreads();
        if (i + 2 < 24) issue(i + 2);

        const float* As = gsm + (i % 3) * 2 * GS_FLOATS;
        const float* Bs = As + GS_FLOATS;
#pragma unroll
        for (int ks = 0; ks < 4; ks++) {
            const int kb = ks * 8;
            uint32_t af[4][4], bf[4][2];
#pragma unroll
            for (int mi = 0; mi < 4; mi++) {
                int rb = wm + mi * 16;
                af[mi][0] = __float_as_uint(tf32r(As[(rb + g) * 36 + kb + tg]));
                af[mi][1] = __float_as_uint(tf32r(As[(rb + g + 8) * 36 + kb + tg]));
                af[mi][2] = __float_as_uint(tf32r(As[(rb + g) * 36 + kb + tg + 4]));
                af[mi][3] = __float_as_uint(tf32r(As[(rb + g + 8) * 36 + kb + tg + 4]));
            }
#pragma unroll
            for (int ni = 0; ni < 4; ni++) {
                int cb = wn + ni * 8;
                bf[ni][0] = __float_as_uint(tf32r(Bs[(cb + g) * 36 + kb + tg]));
                bf[ni][1] = __float_as_uint(tf32r(Bs[(cb + g) * 36 + kb + tg + 4]));
            }
#pragma unroll
            for (int mi = 0; mi < 4; mi++)
#pragma unroll
                for (int ni = 0; ni < 4; ni++)
                    mma8(acc[mi][ni], af[mi], bf[ni][0], bf[ni][1]);
        }
    }

#pragma unroll
    for (int mi = 0; mi < 4; mi++) {
        int r = m0 + wm + mi * 16 + g;
#pragma unroll
        for (int ni = 0; ni < 4; ni++) {
            int c = n0 + wn + ni * 8 + 2 * tg;   // always even
            float v00 = acc[mi][ni][0], v01 = acc[mi][ni][1];
            float v10 = acc[mi][ni][2], v11 = acc[mi][ni][3];
            if (HAS_BIAS) {
                float bx = bias[c], by = bias[c + 1];
                *(float2*)&C[(size_t)r * DM + c] = make_float2(v00 + bx, v01 + by);
                *(float2*)&C[(size_t)(r + 8) * DM + c] = make_float2(v10 + bx, v11 + by);
            } else if (mat < 2) {
                // RoPE: pair (x[2d], x[2d+1]) -> out[d], out[d+32]; tf32-round
                int d = (c & 63) >> 1, hb = c & ~63;
                float2 cs0 = g_rope[r * 32 + d];
                float2 cs1 = g_rope[(r + 8) * 32 + d];
                C[(size_t)r * DM + hb + d]            = tf32r(v00 * cs0.x - v01 * cs0.y);
                C[(size_t)r * DM + hb + d + 32]       = tf32r(v00 * cs0.y + v01 * cs0.x);
                C[(size_t)(r + 8) * DM + hb + d]      = tf32r(v10 * cs1.x - v11 * cs1.y);
                C[(size_t)(r + 8) * DM + hb + d + 32] = tf32r(v10 * cs1.y + v11 * cs1.x);
            } else {
                *(float2*)&C[(size_t)r * DM + c] = make_float2(tf32r(v00), tf32r(v01));
                *(float2*)&C[(size_t)(r + 8) * DM + c] = make_float2(tf32r(v10), tf32r(v11));
            }
        }
    }
}

// ---------------------------------------------------------------------------
// Flash attention, tf32 mma.sync, causal. BQ=128, BK=64, 256 threads.
// 3-stage cp.async KV ring (Q stages in slot 2, dead after extraction).
// P never touches smem: C-frag -> A-frag via quad shuffles (bit-exact).
// Deferred l-reduction; diagonal fully-masked warps skip (exact).
// ---------------------------------------------------------------------------
#define KSS 68
#define VSS 72
#define KVSTG 8960                       // floats: 64*68 + 64*72
#define ATT_SMEM (3 * KVSTG * 4)         // 107520 B

__global__ __launch_bounds__(256, 2) void flash_tf32(
    const float* __restrict__ Q, const float* __restrict__ K,
    const float* __restrict__ V, float* __restrict__ O)
{
    extern __shared__ float sm[];
    const int h  = blockIdx.y;
    const int qb = gridDim.x - 1 - blockIdx.x;   // long causal rows first
    const int q0 = qb * 128;
    const int t = threadIdx.x, lane = t & 31, w = t >> 5;
    const int g = lane >> 2, tg = lane & 3;
    const int s1 = (lane & ~3) | (tg >> 1);      // quad-transpose src lanes
    const int s2 = s1 + 2;
    const bool odd = (tg & 1);

    auto issue_kv = [&](int jb, int st) {
        float* Ks = sm + st * KVSTG;
        float* Vs = Ks + 64 * KSS;
        const int k0 = jb * 64;
#pragma unroll
        for (int it = 0; it < 4; it++) {
            int lin = it * 256 + t, r = lin >> 4, c = (lin & 15) << 2;
            CPA16(s2u(&Ks[r * KSS + c]), &K[(size_t)(k0 + r) * DM + h * HD + c]);
            CPA16(s2u(&Vs[r * VSS + c]), &V[(size_t)(k0 + r) * DM + h * HD + c]);
        }
        CPA_COMMIT();
    };

    // groups: [KV0][Q][KV1]
    issue_kv(0, 0);
    {
        float* QB = sm + 2 * KVSTG;
#pragma unroll
        for (int it = 0; it < 8; it++) {
            int lin = it * 256 + t, r = lin >> 4, c = (lin & 15) << 2;
            CPA16(s2u(&QB[r * 68 + c]), &Q[(size_t)(q0 + r) * DM + h * HD + c]);
        }
        CPA_COMMIT();
    }
    issue_kv(1, 1);

    CPA_WAIT1();          // KV0 + Q complete (KV1 may be in flight)
    __syncthreads();

    uint32_t qf[8][4];
    {
        const uint32_t* QB = (const uint32_t*)(sm + 2 * KVSTG);
#pragma unroll
        for (int ks = 0; ks < 8; ks++) {
            int rb = w * 16, kb = ks * 8;
            qf[ks][0] = QB[(rb + g) * 68 + kb + tg];
            qf[ks][1] = QB[(rb + g + 8) * 68 + kb + tg];
            qf[ks][2] = QB[(rb + g) * 68 + kb + tg + 4];
            qf[ks][3] = QB[(rb + g + 8) * 68 + kb + tg + 4];
        }
    }

    float m0r = -1e30f, m1r = -1e30f, l0 = 0.0f, l1 = 0.0f;
    float ao[8][4];
#pragma unroll
    for (int nt = 0; nt < 8; nt++)
#pragma unroll
        for (int c = 0; c < 4; c++) ao[nt][c] = 0.0f;

    const int jbmax = 2 * qb + 1;

    for (int jb = 0; jb <= jbmax; jb++) {
        CPA_WAIT1();          // KV(jb) landed (KV(jb+1) may be in flight)
        __syncthreads();      // visibility + all warps done with stage jb-1
        if (jb + 2 <= jbmax) issue_kv(jb + 2, (jb + 2) % 3);

        const int k0 = jb * 64;
        const int off = k0 - q0;
        // off==64: warps 0-3 (rows < 64) fully masked -> exact skip
        if (off == 64 && w < 4) continue;

        const uint32_t* Ks = (const uint32_t*)(sm + (jb % 3) * KVSTG);
        const uint32_t* Vs = Ks + 64 * KSS;

        // S = Q K^T
        float sc[8][4];
#pragma unroll
        for (int nt = 0; nt < 8; nt++)
#pragma unroll
            for (int c = 0; c < 4; c++) sc[nt][c] = 0.0f;

#pragma unroll
        for (int ks = 0; ks < 8; ks++) {
            const int kb = ks * 8;
#pragma unroll
            for (int nt = 0; nt < 8; nt++) {
                uint32_t b0 = Ks[(nt * 8 + g) * KSS + kb + tg];
                uint32_t b1 = Ks[(nt * 8 + g) * KSS + kb + tg + 4];
                mma8(sc[nt], qf[ks], b0, b1);
            }
        }

        // scale + causal mask
        const float scl = 0.125f;
        if (off >= 0) {
            int lim0 = w * 16 + g - off, lim1 = lim0 + 8;
#pragma unroll
            for (int nt = 0; nt < 8; nt++) {
                int c0 = nt * 8 + 2 * tg, c1 = c0 + 1;
                sc[nt][0] = (c0 <= lim0) ? sc[nt][0] * scl : -1e9f;
                sc[nt][1] = (c1 <= lim0) ? sc[nt][1] * scl : -1e9f;
                sc[nt][2] = (c0 <= lim1) ? sc[nt][2] * scl : -1e9f;
                sc[nt][3] = (c1 <= lim1) ? sc[nt][3] * scl : -1e9f;
            }
        } else {
#pragma unroll
            for (int nt = 0; nt < 8; nt++)
#pragma unroll
                for (int c = 0; c < 4; c++) sc[nt][c] *= scl;
        }

        // online softmax
        float mx0 = -1e30f, mx1 = -1e30f;
#pragma unroll
        for (int nt = 0; nt < 8; nt++) {
            mx0 = fmaxf(mx0, fmaxf(sc[nt][0], sc[nt][1]));
            mx1 = fmaxf(mx1, fmaxf(sc[nt][2], sc[nt][3]));
        }
        mx0 = fmaxf(mx0, __shfl_xor_sync(0xffffffffu, mx0, 1));
        mx0 = fmaxf(mx0, __shfl_xor_sync(0xffffffffu, mx0, 2));
        mx1 = fmaxf(mx1, __shfl_xor_sync(0xffffffffu, mx1, 1));
        mx1 = fmaxf(mx1, __shfl_xor_sync(0xffffffffu, mx1, 2));

        float mn0 = fmaxf(m0r, mx0), mn1 = fmaxf(m1r, mx1);
        float al0 = __expf(m0r - mn0), al1 = __expf(m1r - mn1);
        m0r = mn0; m1r = mn1;

        float rs0 = 0.0f, rs1 = 0.0f;
#pragma unroll
        for (int nt = 0; nt < 8; nt++) {
            sc[nt][0] = __expf(sc[nt][0] - mn0);
            sc[nt][1] = __expf(sc[nt][1] - mn0);
            sc[nt][2] = __expf(sc[nt][2] - mn1);
            sc[nt][3] = __expf(sc[nt][3] - mn1);
            rs0 += sc[nt][0] + sc[nt][1];
            rs1 += sc[nt][2] + sc[nt][3];
        }
        l0 = l0 * al0 + rs0;      // per-lane partial; exact (al uniform in quad)
        l1 = l1 * al1 + rs1;
#pragma unroll
        for (int nt = 0; nt < 8; nt++) {
            ao[nt][0] *= al0; ao[nt][1] *= al0;
            ao[nt][2] *= al1; ao[nt][3] *= al1;
        }

        // O += P V : P C-frag -> A-frag via quad shuffles (no smem)
#pragma unroll
        for (int ks = 0; ks < 8; ks++) {
            const int kb = ks * 8;
            float p0 = tf32r(sc[ks][0]), p1 = tf32r(sc[ks][1]);
            float p2 = tf32r(sc[ks][2]), p3 = tf32r(sc[ks][3]);
            float t00 = __shfl_sync(0xffffffffu, p0, s1);
            float t01 = __shfl_sync(0xffffffffu, p1, s1);
            float t10 = __shfl_sync(0xffffffffu, p2, s1);
            float t11 = __shfl_sync(0xffffffffu, p3, s1);
            float t20 = __shfl_sync(0xffffffffu, p0, s2);
            float t21 = __shfl_sync(0xffffffffu, p1, s2);
            float t30 = __shfl_sync(0xffffffffu, p2, s2);
            float t31 = __shfl_sync(0xffffffffu, p3, s2);
            uint32_t pf[4];
            pf[0] = __float_as_uint(odd ? t01 : t00);   // P[g][kb+tg]
            pf[1] = __float_as_uint(odd ? t11 : t10);   // P[g+8][kb+tg]
            pf[2] = __float_as_uint(odd ? t21 : t20);   // P[g][kb+tg+4]
            pf[3] = __float_as_uint(odd ? t31 : t30);   // P[g+8][kb+tg+4]
#pragma unroll
            for (int nt = 0; nt < 8; nt++) {
                uint32_t b0 = Vs[(kb + tg) * VSS + nt * 8 + g];
                uint32_t b1 = Vs[(kb + tg + 4) * VSS + nt * 8 + g];
                mma8(ao[nt], pf, b0, b1);
            }
        }
    }

    // epilogue: reduce deferred l across the 4-lane group, normalize, store
    l0 += __shfl_xor_sync(0xffffffffu, l0, 1);
    l0 += __shfl_xor_sync(0xffffffffu, l0, 2);
    l1 += __shfl_xor_sync(0xffffffffu, l1, 1);
    l1 += __shfl_xor_sync(0xffffffffu, l1, 2);
    float inv0 = 1.0f / l0, inv1 = 1.0f / l1;
    int r0 = q0 + w * 16 + g, r1 = r0 + 8;
#pragma unroll
    for (int nt = 0; nt < 8; nt++) {
        int c = nt * 8 + 2 * tg;
        *(float2*)&O[(size_t)r0 * DM + h * HD + c] =
            make_float2(tf32r(ao[nt][0] * inv0), tf32r(ao[nt][1] * inv0));
        *(float2*)&O[(size_t)r1 * DM + h * HD + c] =
            make_float2(tf32r(ao[nt][2] * inv1), tf32r(ao[nt][3] * inv1));
    }
}

// ---------------------------------------------------------------------------
// Launch
// ---------------------------------------------------------------------------
extern "C" void kernel_launch(void* const* d_in, const int* in_sizes, int n_in,
                              void* d_out, int out_size)
{
    (void)in_sizes; (void)n_in; (void)out_size;
    const float* x  = (const float*)d_in[0];
    const float* Wq = (const float*)d_in[2];
    const float* Wk = (const float*)d_in[3];
    const float* Wv = (const float*)d_in[4];
    const float* Wo = (const float*)d_in[5];
    const float* bo = (const float*)d_in[6];
    float* out = (float*)d_out;

    float *Qp, *Kp, *Vp, *AO;
    cudaGetSymbolAddress((void**)&Qp, g_Q);
    cudaGetSymbolAddress((void**)&Kp, g_K);
    cudaGetSymbolAddress((void**)&Vp, g_V);
    cudaGetSymbolAddress((void**)&AO, g_AO);

    cudaFuncSetAttribute(flash_tf32,
                         cudaFuncAttributeMaxDynamicSharedMemorySize, ATT_SMEM);
    cudaFuncSetAttribute(gemm_tf32<false>,
                         cudaFuncAttributeMaxDynamicSharedMemorySize, GEMM_SMEM);
    cudaFuncSetAttribute(gemm_tf32<true>,
                         cudaFuncAttributeMaxDynamicSharedMemorySize, GEMM_SMEM);

    // RoPE tables (must precede the QKV GEMM epilogue)
    invfreq_kernel<<<1, 32>>>();
    rope_table_kernel<<<(SEQ * 32) / 256, 256>>>();

    // Fused QKV projection + RoPE + tf32 pre-round
    gemm_tf32<false><<<dim3(18, 32), 256, GEMM_SMEM>>>(
        x, Wq, Wk, Wv, nullptr, Qp, Kp, Vp);

    flash_tf32<<<dim3(SEQ / 128, NH), 256, ATT_SMEM>>>(Qp, Kp, Vp, AO);

    // Output projection + bias
    gemm_tf32<true><<<dim3(6, 32), 256, GEMM_SMEM>>>(
        AO, Wo, Wo, Wo, bo, out, out, out);
}

// round 16
// speedup vs baseline: 2.5944x; 1.0011x over previous
#include <cuda_runtime.h>
#include <cstdint>
#include <math.h>

#define SEQ 4096
#define DM  768
#define NH  12
#define HD  64

// Scratch (allocation-free rule: __device__ globals)
__device__ float  g_Q[SEQ * DM];
__device__ float  g_K[SEQ * DM];
__device__ float  g_V[SEQ * DM];
__device__ float  g_AO[SEQ * DM];
__device__ float  g_invf[32];
__device__ float2 g_rope[SEQ * 32];

__device__ __forceinline__ float tf32r(float x) {
    float r; asm("cvt.rna.tf32.f32 %0, %1;" : "=f"(r) : "f"(x)); return r;
}
__device__ __forceinline__ void mma8(float c[4], const uint32_t a[4],
                                     uint32_t b0, uint32_t b1) {
    asm volatile(
        "mma.sync.aligned.m16n8k8.row.col.f32.tf32.tf32.f32 "
        "{%0,%1,%2,%3}, {%4,%5,%6,%7}, {%8,%9}, {%0,%1,%2,%3};"
        : "+f"(c[0]), "+f"(c[1]), "+f"(c[2]), "+f"(c[3])
        : "r"(a[0]), "r"(a[1]), "r"(a[2]), "r"(a[3]), "r"(b0), "r"(b1));
}
__device__ __forceinline__ uint32_t s2u(const void* p) {
    return (uint32_t)__cvta_generic_to_shared(p);
}
#define CPA16(dst, src) \
    asm volatile("cp.async.ca.shared.global [%0], [%1], 16;" :: "r"(dst), "l"(src))
#define CPA_COMMIT() asm volatile("cp.async.commit_group;" ::: "memory")
#define CPA_WAIT0()  asm volatile("cp.async.wait_group 0;" ::: "memory")
#define CPA_WAIT1()  asm volatile("cp.async.wait_group 1;" ::: "memory")

// ---------------------------------------------------------------------------
// RoPE tables
// ---------------------------------------------------------------------------
__global__ void invfreq_kernel() {
    int d = threadIdx.x;   // 32 threads
    g_invf[d] = (float)exp(-(double)(2 * d) / 64.0 * log(10000.0));
}

__global__ __launch_bounds__(256) void rope_table_kernel() {
    int i = blockIdx.x * 256 + threadIdx.x;   // SEQ*32 threads
    int s = i >> 5, d = i & 31;
    float ang = (float)s * g_invf[d];
    float sn, cs;
    sincosf(ang, &sn, &cs);
    g_rope[i] = make_float2(cs, sn);
}

// ---------------------------------------------------------------------------
// TF32 GEMM (mma.sync), cp.async 3-stage smem pipeline + register
// double-buffered fragments (prefetch ks+1 during mma of ks; all frag-array
// subscripts compile-time constants after full unroll).
// 256 threads, warp tile 64x32. C = A @ W^T; QKV fused (mat = blockIdx.x/6).
// ---------------------------------------------------------------------------
#define GS_FLOATS (128 * 36)
#define GEMM_SMEM (3 * 2 * GS_FLOATS * 4)

template <bool HAS_BIAS>
__global__ __launch_bounds__(256, 2) void gemm_tf32(
    const float* __restrict__ A,
    const float* __restrict__ W0, const float* __restrict__ W1,
    const float* __restrict__ W2,
    const float* __restrict__ bias,
    float* __restrict__ C0, float* __restrict__ C1, float* __restrict__ C2)
{
    extern __shared__ float gsm[];

    const int m0  = blockIdx.y * 128;
    const int nt  = blockIdx.x;
    const int mat = nt / 6;
    const int n0  = (nt % 6) * 128;
    const float* W = (mat == 0) ? W0 : (mat == 1) ? W1 : W2;
    float*       C = (mat == 0) ? C0 : (mat == 1) ? C1 : C2;

    const int t = threadIdx.x, lane = t & 31, wid = t >> 5;
    const int g = lane >> 2, tg = lane & 3;
    const int wm = (wid & 1) * 64, wn = (wid >> 1) * 32;
    const int r_ld = t >> 3, c_ld = (t & 7) << 2;

    float acc[4][4][4] = {};

    auto issue = [&](int slab) {
        float* As = gsm + (slab % 3) * 2 * GS_FLOATS;
        float* Bs = As + GS_FLOATS;
        const int k0 = slab * 32;
#pragma unroll
        for (int it = 0; it < 4; it++) {
            int r = it * 32 + r_ld;
            CPA16(s2u(&As[r * 36 + c_ld]), &A[(size_t)(m0 + r) * DM + k0 + c_ld]);
            CPA16(s2u(&Bs[r * 36 + c_ld]), &W[(size_t)(n0 + r) * DM + k0 + c_ld]);
        }
        CPA_COMMIT();
    };
    issue(0);
    issue(1);

    uint32_t af[2][4][4], bf[2][4][2];
    auto ldfrag = [&](int buf, const float* As, const float* Bs, int ks) {
        const int kb = ks * 8;
#pragma unroll
        for (int mi = 0; mi < 4; mi++) {
            int rb = wm + mi * 16;
            af[buf][mi][0] = __float_as_uint(tf32r(As[(rb + g) * 36 + kb + tg]));
            af[buf][mi][1] = __float_as_uint(tf32r(As[(rb + g + 8) * 36 + kb + tg]));
            af[buf][mi][2] = __float_as_uint(tf32r(As[(rb + g) * 36 + kb + tg + 4]));
            af[buf][mi][3] = __float_as_uint(tf32r(As[(rb + g + 8) * 36 + kb + tg + 4]));
        }
#pragma unroll
        for (int ni = 0; ni < 4; ni++) {
            int cb = wn + ni * 8;
            bf[buf][ni][0] = __float_as_uint(tf32r(Bs[(cb + g) * 36 + kb + tg]));
            bf[buf][ni][1] = __float_as_uint(tf32r(Bs[(cb + g) * 36 + kb + tg + 4]));
        }
    };

    for (int i = 0; i < 24; i++) {
        if (i < 22) CPA_WAIT1(); else CPA_WAIT0();
        __syncthreads();
        if (i + 2 < 24) issue(i + 2);

        const float* As = gsm + (i % 3) * 2 * GS_FLOATS;
        const float* Bs = As + GS_FLOATS;
        ldfrag(0, As, Bs, 0);
#pragma unroll
        for (int ks = 0; ks < 4; ks++) {
            const int cur = ks & 1;          // compile-time const per unroll
            if (ks < 3) ldfrag(cur ^ 1, As, Bs, ks + 1);
#pragma unroll
            for (int mi = 0; mi < 4; mi++)
#pragma unroll
                for (int ni = 0; ni < 4; ni++)
                    mma8(acc[mi][ni], af[cur][mi], bf[cur][ni][0], bf[cur][ni][1]);
        }
    }

#pragma unroll
    for (int mi = 0; mi < 4; mi++) {
        int r = m0 + wm + mi * 16 + g;
#pragma unroll
        for (int ni = 0; ni < 4; ni++) {
            int c = n0 + wn + ni * 8 + 2 * tg;   // always even
            float v00 = acc[mi][ni][0], v01 = acc[mi][ni][1];
            float v10 = acc[mi][ni][2], v11 = acc[mi][ni][3];
            if (HAS_BIAS) {
                float bx = bias[c], by = bias[c + 1];
                *(float2*)&C[(size_t)r * DM + c] = make_float2(v00 + bx, v01 + by);
                *(float2*)&C[(size_t)(r + 8) * DM + c] = make_float2(v10 + bx, v11 + by);
            } else if (mat < 2) {
                // RoPE: pair (x[2d], x[2d+1]) -> out[d], out[d+32]; tf32-round
                int d = (c & 63) >> 1, hb = c & ~63;
                float2 cs0 = g_rope[r * 32 + d];
                float2 cs1 = g_rope[(r + 8) * 32 + d];
                C[(size_t)r * DM + hb + d]            = tf32r(v00 * cs0.x - v01 * cs0.y);
                C[(size_t)r * DM + hb + d + 32]       = tf32r(v00 * cs0.y + v01 * cs0.x);
                C[(size_t)(r + 8) * DM + hb + d]      = tf32r(v10 * cs1.x - v11 * cs1.y);
                C[(size_t)(r + 8) * DM + hb + d + 32] = tf32r(v10 * cs1.y + v11 * cs1.x);
            } else {
                *(float2*)&C[(size_t)r * DM + c] = make_float2(tf32r(v00), tf32r(v01));
                *(float2*)&C[(size_t)(r + 8) * DM + c] = make_float2(tf32r(v10), tf32r(v11));
            }
        }
    }
}

// ---------------------------------------------------------------------------
// Flash attention, tf32 mma.sync, causal. BQ=128, BK=64, 256 threads.
// BYTE-IDENTICAL to the round-10/15 measured-best kernel. DO NOT TOUCH:
// this schedule is a fragile local optimum (R13/R14 evidence).
// ---------------------------------------------------------------------------
#define KSS 68
#define VSS 72
#define KVSTG 8960                       // floats: 64*68 + 64*72
#define ATT_SMEM (3 * KVSTG * 4)         // 107520 B

__global__ __launch_bounds__(256, 2) void flash_tf32(
    const float* __restrict__ Q, const float* __restrict__ K,
    const float* __restrict__ V, float* __restrict__ O)
{
    extern __shared__ float sm[];
    const int h  = blockIdx.y;
    const int qb = gridDim.x - 1 - blockIdx.x;   // long causal rows first
    const int q0 = qb * 128;
    const int t = threadIdx.x, lane = t & 31, w = t >> 5;
    const int g = lane >> 2, tg = lane & 3;
    const int s1 = (lane & ~3) | (tg >> 1);      // quad-transpose src lanes
    const int s2 = s1 + 2;
    const bool odd = (tg & 1);

    auto issue_kv = [&](int jb, int st) {
        float* Ks = sm + st * KVSTG;
        float* Vs = Ks + 64 * KSS;
        const int k0 = jb * 64;
#pragma unroll
        for (int it = 0; it < 4; it++) {
            int lin = it * 256 + t, r = lin >> 4, c = (lin & 15) << 2;
            CPA16(s2u(&Ks[r * KSS + c]), &K[(size_t)(k0 + r) * DM + h * HD + c]);
            CPA16(s2u(&Vs[r * VSS + c]), &V[(size_t)(k0 + r) * DM + h * HD + c]);
        }
        CPA_COMMIT();
    };

    // groups: [KV0][Q][KV1]
    issue_kv(0, 0);
    {
        float* QB = sm + 2 * KVSTG;
#pragma unroll
        for (int it = 0; it < 8; it++) {
            int lin = it * 256 + t, r = lin >> 4, c = (lin & 15) << 2;
            CPA16(s2u(&QB[r * 68 + c]), &Q[(size_t)(q0 + r) * DM + h * HD + c]);
        }
        CPA_COMMIT();
    }
    issue_kv(1, 1);

    CPA_WAIT1();          // KV0 + Q complete (KV1 may be in flight)
    __syncthreads();

    uint32_t qf[8][4];
    {
        const uint32_t* QB = (const uint32_t*)(sm + 2 * KVSTG);
#pragma unroll
        for (int ks = 0; ks < 8; ks++) {
            int rb = w * 16, kb = ks * 8;
            qf[ks][0] = QB[(rb + g) * 68 + kb + tg];
            qf[ks][1] = QB[(rb + g + 8) * 68 + kb + tg];
            qf[ks][2] = QB[(rb + g) * 68 + kb + tg + 4];
            qf[ks][3] = QB[(rb + g + 8) * 68 + kb + tg + 4];
        }
    }

    float m0r = -1e30f, m1r = -1e30f, l0 = 0.0f, l1 = 0.0f;
    float ao[8][4];
#pragma unroll
    for (int nt = 0; nt < 8; nt++)
#pragma unroll
        for (int c = 0; c < 4; c++) ao[nt][c] = 0.0f;

    const int jbmax = 2 * qb + 1;

    for (int jb = 0; jb <= jbmax; jb++) {
        CPA_WAIT1();          // KV(jb) landed (KV(jb+1) may be in flight)
        __syncthreads();      // visibility + all warps done with stage jb-1
        if (jb + 2 <= jbmax) issue_kv(jb + 2, (jb + 2) % 3);

        const int k0 = jb * 64;
        const int off = k0 - q0;
        // off==64: warps 0-3 (rows < 64) fully masked -> exact skip
        if (off == 64 && w < 4) continue;

        const uint32_t* Ks = (const uint32_t*)(sm + (jb % 3) * KVSTG);
        const uint32_t* Vs = Ks + 64 * KSS;

        // S = Q K^T
        float sc[8][4];
#pragma unroll
        for (int nt = 0; nt < 8; nt++)
#pragma unroll
            for (int c = 0; c < 4; c++) sc[nt][c] = 0.0f;

#pragma unroll
        for (int ks = 0; ks < 8; ks++) {
            const int kb = ks * 8;
#pragma unroll
            for (int nt = 0; nt < 8; nt++) {
                uint32_t b0 = Ks[(nt * 8 + g) * KSS + kb + tg];
                uint32_t b1 = Ks[(nt * 8 + g) * KSS + kb + tg + 4];
                mma8(sc[nt], qf[ks], b0, b1);
            }
        }

        // scale + causal mask
        const float scl = 0.125f;
        if (off >= 0) {
            int lim0 = w * 16 + g - off, lim1 = lim0 + 8;
#pragma unroll
            for (int nt = 0; nt < 8; nt++) {
                int c0 = nt * 8 + 2 * tg, c1 = c0 + 1;
                sc[nt][0] = (c0 <= lim0) ? sc[nt][0] * scl : -1e9f;
                sc[nt][1] = (c1 <= lim0) ? sc[nt][1] * scl : -1e9f;
                sc[nt][2] = (c0 <= lim1) ? sc[nt][2] * scl : -1e9f;
                sc[nt][3] = (c1 <= lim1) ? sc[nt][3] * scl : -1e9f;
            }
        } else {
#pragma unroll
            for (int nt = 0; nt < 8; nt++)
#pragma unroll
                for (int c = 0; c < 4; c++) sc[nt][c] *= scl;
        }

        // online softmax
        float mx0 = -1e30f, mx1 = -1e30f;
#pragma unroll
        for (int nt = 0; nt < 8; nt++) {
            mx0 = fmaxf(mx0, fmaxf(sc[nt][0], sc[nt][1]));
            mx1 = fmaxf(mx1, fmaxf(sc[nt][2], sc[nt][3]));
        }
        mx0 = fmaxf(mx0, __shfl_xor_sync(0xffffffffu, mx0, 1));
        mx0 = fmaxf(mx0, __shfl_xor_sync(0xffffffffu, mx0, 2));
        mx1 = fmaxf(mx1, __shfl_xor_sync(0xffffffffu, mx1, 1));
        mx1 = fmaxf(mx1, __shfl_xor_sync(0xffffffffu, mx1, 2));

        float mn0 = fmaxf(m0r, mx0), mn1 = fmaxf(m1r, mx1);
        float al0 = __expf(m0r - mn0), al1 = __expf(m1r - mn1);
        m0r = mn0; m1r = mn1;

        float rs0 = 0.0f, rs1 = 0.0f;
#pragma unroll
        for (int nt = 0; nt < 8; nt++) {
            sc[nt][0] = __expf(sc[nt][0] - mn0);
            sc[nt][1] = __expf(sc[nt][1] - mn0);
            sc[nt][2] = __expf(sc[nt][2] - mn1);
            sc[nt][3] = __expf(sc[nt][3] - mn1);
            rs0 += sc[nt][0] + sc[nt][1];
            rs1 += sc[nt][2] + sc[nt][3];
        }
        l0 = l0 * al0 + rs0;      // per-lane partial; exact (al uniform in quad)
        l1 = l1 * al1 + rs1;
#pragma unroll
        for (int nt = 0; nt < 8; nt++) {
            ao[nt][0] *= al0; ao[nt][1] *= al0;
            ao[nt][2] *= al1; ao[nt][3] *= al1;
        }

        // O += P V : P C-frag -> A-frag via quad shuffles (no smem)
#pragma unroll
        for (int ks = 0; ks < 8; ks++) {
            const int kb = ks * 8;
            float p0 = tf32r(sc[ks][0]), p1 = tf32r(sc[ks][1]);
            float p2 = tf32r(sc[ks][2]), p3 = tf32r(sc[ks][3]);
            float t00 = __shfl_sync(0xffffffffu, p0, s1);
            float t01 = __shfl_sync(0xffffffffu, p1, s1);
            float t10 = __shfl_sync(0xffffffffu, p2, s1);
            float t11 = __shfl_sync(0xffffffffu, p3, s1);
            float t20 = __shfl_sync(0xffffffffu, p0, s2);
            float t21 = __shfl_sync(0xffffffffu, p1, s2);
            float t30 = __shfl_sync(0xffffffffu, p2, s2);
            float t31 = __shfl_sync(0xffffffffu, p3, s2);
            uint32_t pf[4];
            pf[0] = __float_as_uint(odd ? t01 : t00);   // P[g][kb+tg]
            pf[1] = __float_as_uint(odd ? t11 : t10);   // P[g+8][kb+tg]
            pf[2] = __float_as_uint(odd ? t21 : t20);   // P[g][kb+tg+4]
            pf[3] = __float_as_uint(odd ? t31 : t30);   // P[g+8][kb+tg+4]
#pragma unroll
            for (int nt = 0; nt < 8; nt++) {
                uint32_t b0 = Vs[(kb + tg) * VSS + nt * 8 + g];
                uint32_t b1 = Vs[(kb + tg + 4) * VSS + nt * 8 + g];
                mma8(ao[nt], pf, b0, b1);
            }
        }
    }

    // epilogue: reduce deferred l across the 4-lane group, normalize, store
    l0 += __shfl_xor_sync(0xffffffffu, l0, 1);
    l0 += __shfl_xor_sync(0xffffffffu, l0, 2);
    l1 += __shfl_xor_sync(0xffffffffu, l1, 1);
    l1 += __shfl_xor_sync(0xffffffffu, l1, 2);
    float inv0 = 1.0f / l0, inv1 = 1.0f / l1;
    int r0 = q0 + w * 16 + g, r1 = r0 + 8;
#pragma unroll
    for (int nt = 0; nt < 8; nt++) {
        int c = nt * 8 + 2 * tg;
        *(float2*)&O[(size_t)r0 * DM + h * HD + c] =
            make_float2(tf32r(ao[nt][0] * inv0), tf32r(ao[nt][1] * inv0));
        *(float2*)&O[(size_t)r1 * DM + h * HD + c] =
            make_float2(tf32r(ao[nt][2] * inv1), tf32r(ao[nt][3] * inv1));
    }
}

// ---------------------------------------------------------------------------
// Launch
// ---------------------------------------------------------------------------
extern "C" void kernel_launch(void* const* d_in, const int* in_sizes, int n_in,
                              void* d_out, int out_size)
{
    (void)in_sizes; (void)n_in; (void)out_size;
    const float* x  = (const float*)d_in[0];
    const float* Wq = (const float*)d_in[2];
    const float* Wk = (const float*)d_in[3];
    const float* Wv = (const float*)d_in[4];
    const float* Wo = (const float*)d_in[5];
    const float* bo = (const float*)d_in[6];
    float* out = (float*)d_out;

    float *Qp, *Kp, *Vp, *AO;
    cudaGetSymbolAddress((void**)&Qp, g_Q);
    cudaGetSymbolAddress((void**)&Kp, g_K);
    cudaGetSymbolAddress((void**)&Vp, g_V);
    cudaGetSymbolAddress((void**)&AO, g_AO);

    cudaFuncSetAttribute(flash_tf32,
                         cudaFuncAttributeMaxDynamicSharedMemorySize, ATT_SMEM);
    cudaFuncSetAttribute(gemm_tf32<false>,
                         cudaFuncAttributeMaxDynamicSharedMemorySize, GEMM_SMEM);
    cudaFuncSetAttribute(gemm_tf32<true>,
                         cudaFuncAttributeMaxDynamicSharedMemorySize, GEMM_SMEM);

    // RoPE tables (must precede the QKV GEMM epilogue)
    invfreq_kernel<<<1, 32>>>();
    rope_table_kernel<<<(SEQ * 32) / 256, 256>>>();

    // Fused QKV projection + RoPE + tf32 pre-round
    gemm_tf32<false><<<dim3(18, 32), 256, GEMM_SMEM>>>(
        x, Wq, Wk, Wv, nullptr, Qp, Kp, Vp);

    flash_tf32<<<dim3(SEQ / 128, NH), 256, ATT_SMEM>>>(Qp, Kp, Vp, AO);

    // Output projection + bias
    gemm_tf32<true><<<dim3(6, 32), 256, GEMM_SMEM>>>(
        AO, Wo, Wo, Wo, bo, out, out, out);
}

// round 17
// speedup vs baseline: 2.6279x; 1.0129x over previous
#include <cuda_runtime.h>
#include <cstdint>
#include <math.h>

#define SEQ 4096
#define DM  768
#define NH  12
#define HD  64

// Scratch (allocation-free rule: __device__ globals)
__device__ float  g_Q[SEQ * DM];
__device__ float  g_K[SEQ * DM];
__device__ float  g_V[SEQ * DM];
__device__ float  g_AO[SEQ * DM];
__device__ float  g_invf[32];
__device__ float2 g_rope[SEQ * 32];

__device__ __forceinline__ float tf32r(float x) {
    float r; asm("cvt.rna.tf32.f32 %0, %1;" : "=f"(r) : "f"(x)); return r;
}
__device__ __forceinline__ void mma8(float c[4], const uint32_t a[4],
                                     uint32_t b0, uint32_t b1) {
    asm volatile(
        "mma.sync.aligned.m16n8k8.row.col.f32.tf32.tf32.f32 "
        "{%0,%1,%2,%3}, {%4,%5,%6,%7}, {%8,%9}, {%0,%1,%2,%3};"
        : "+f"(c[0]), "+f"(c[1]), "+f"(c[2]), "+f"(c[3])
        : "r"(a[0]), "r"(a[1]), "r"(a[2]), "r"(a[3]), "r"(b0), "r"(b1));
}
__device__ __forceinline__ uint32_t s2u(const void* p) {
    return (uint32_t)__cvta_generic_to_shared(p);
}
#define CPA16(dst, src) \
    asm volatile("cp.async.ca.shared.global [%0], [%1], 16;" :: "r"(dst), "l"(src))
#define CPA_COMMIT() asm volatile("cp.async.commit_group;" ::: "memory")
#define CPA_WAIT0()  asm volatile("cp.async.wait_group 0;" ::: "memory")
#define CPA_WAIT1()  asm volatile("cp.async.wait_group 1;" ::: "memory")

// ---------------------------------------------------------------------------
// RoPE tables
// ---------------------------------------------------------------------------
__global__ void invfreq_kernel() {
    int d = threadIdx.x;   // 32 threads
    g_invf[d] = (float)exp(-(double)(2 * d) / 64.0 * log(10000.0));
}

__global__ __launch_bounds__(256) void rope_table_kernel() {
    int i = blockIdx.x * 256 + threadIdx.x;   // SEQ*32 threads
    int s = i >> 5, d = i & 31;
    float ang = (float)s * g_invf[d];
    float sn, cs;
    sincosf(ang, &sn, &cs);
    g_rope[i] = make_float2(cs, sn);
}

// ---------------------------------------------------------------------------
// TF32 GEMM (mma.sync), cp.async 3-stage smem pipeline + reg double-buffer.
// Templated on MT (m-tiles of 16 per warp): MT=4 -> 128-row CTA tile
// (identical to measured config), MT=2 -> 64-row tile (out-GEMM wave packing).
// 256 threads, warp tile (MT*16)x32. C = A @ W^T; QKV fused via mat select.
// ---------------------------------------------------------------------------
#define GS_FLOATS (128 * 36)
#define GEMM_SMEM (3 * 2 * GS_FLOATS * 4)

template <bool HAS_BIAS, int MT>
__global__ __launch_bounds__(256, 2) void gemm_tf32(
    const float* __restrict__ A,
    const float* __restrict__ W0, const float* __restrict__ W1,
    const float* __restrict__ W2,
    const float* __restrict__ bias,
    float* __restrict__ C0, float* __restrict__ C1, float* __restrict__ C2)
{
    extern __shared__ float gsm[];

    const int m0  = blockIdx.y * (MT * 32);
    const int nt  = blockIdx.x;
    const int mat = nt / 6;
    const int n0  = (nt % 6) * 128;
    const float* W = (mat == 0) ? W0 : (mat == 1) ? W1 : W2;
    float*       C = (mat == 0) ? C0 : (mat == 1) ? C1 : C2;

    const int t = threadIdx.x, lane = t & 31, wid = t >> 5;
    const int g = lane >> 2, tg = lane & 3;
    const int wm = (wid & 1) * (MT * 16), wn = (wid >> 1) * 32;
    const int r_ld = t >> 3, c_ld = (t & 7) << 2;

    float acc[MT][4][4] = {};

    auto issue = [&](int slab) {
        float* As = gsm + (slab % 3) * 2 * GS_FLOATS;
        float* Bs = As + GS_FLOATS;
        const int k0 = slab * 32;
#pragma unroll
        for (int it = 0; it < MT; it++) {
            int r = it * 32 + r_ld;
            CPA16(s2u(&As[r * 36 + c_ld]), &A[(size_t)(m0 + r) * DM + k0 + c_ld]);
        }
#pragma unroll
        for (int it = 0; it < 4; it++) {
            int r = it * 32 + r_ld;
            CPA16(s2u(&Bs[r * 36 + c_ld]), &W[(size_t)(n0 + r) * DM + k0 + c_ld]);
        }
        CPA_COMMIT();
    };
    issue(0);
    issue(1);

    uint32_t af[2][MT][4], bf[2][4][2];
    auto ldfrag = [&](int buf, const float* As, const float* Bs, int ks) {
        const int kb = ks * 8;
#pragma unroll
        for (int mi = 0; mi < MT; mi++) {
            int rb = wm + mi * 16;
            af[buf][mi][0] = __float_as_uint(tf32r(As[(rb + g) * 36 + kb + tg]));
            af[buf][mi][1] = __float_as_uint(tf32r(As[(rb + g + 8) * 36 + kb + tg]));
            af[buf][mi][2] = __float_as_uint(tf32r(As[(rb + g) * 36 + kb + tg + 4]));
            af[buf][mi][3] = __float_as_uint(tf32r(As[(rb + g + 8) * 36 + kb + tg + 4]));
        }
#pragma unroll
        for (int ni = 0; ni < 4; ni++) {
            int cb = wn + ni * 8;
            bf[buf][ni][0] = __float_as_uint(tf32r(Bs[(cb + g) * 36 + kb + tg]));
            bf[buf][ni][1] = __float_as_uint(tf32r(Bs[(cb + g) * 36 + kb + tg + 4]));
        }
    };

    for (int i = 0; i < 24; i++) {
        if (i < 22) CPA_WAIT1(); else CPA_WAIT0();
        __syncthreads();
        if (i + 2 < 24) issue(i + 2);

        const float* As = gsm + (i % 3) * 2 * GS_FLOATS;
        const float* Bs = As + GS_FLOATS;
        ldfrag(0, As, Bs, 0);
#pragma unroll
        for (int ks = 0; ks < 4; ks++) {
            const int cur = ks & 1;          // compile-time const per unroll
            if (ks < 3) ldfrag(cur ^ 1, As, Bs, ks + 1);
#pragma unroll
            for (int mi = 0; mi < MT; mi++)
#pragma unroll
                for (int ni = 0; ni < 4; ni++)
                    mma8(acc[mi][ni], af[cur][mi], bf[cur][ni][0], bf[cur][ni][1]);
        }
    }

#pragma unroll
    for (int mi = 0; mi < MT; mi++) {
        int r = m0 + wm + mi * 16 + g;
#pragma unroll
        for (int ni = 0; ni < 4; ni++) {
            int c = n0 + wn + ni * 8 + 2 * tg;   // always even
            float v00 = acc[mi][ni][0], v01 = acc[mi][ni][1];
            float v10 = acc[mi][ni][2], v11 = acc[mi][ni][3];
            if (HAS_BIAS) {
                float bx = bias[c], by = bias[c + 1];
                *(float2*)&C[(size_t)r * DM + c] = make_float2(v00 + bx, v01 + by);
                *(float2*)&C[(size_t)(r + 8) * DM + c] = make_float2(v10 + bx, v11 + by);
            } else if (mat < 2) {
                // RoPE: pair (x[2d], x[2d+1]) -> out[d], out[d+32]; tf32-round
                int d = (c & 63) >> 1, hb = c & ~63;
                float2 cs0 = g_rope[r * 32 + d];
                float2 cs1 = g_rope[(r + 8) * 32 + d];
                C[(size_t)r * DM + hb + d]            = tf32r(v00 * cs0.x - v01 * cs0.y);
                C[(size_t)r * DM + hb + d + 32]       = tf32r(v00 * cs0.y + v01 * cs0.x);
                C[(size_t)(r + 8) * DM + hb + d]      = tf32r(v10 * cs1.x - v11 * cs1.y);
                C[(size_t)(r + 8) * DM + hb + d + 32] = tf32r(v10 * cs1.y + v11 * cs1.x);
            } else {
                *(float2*)&C[(size_t)r * DM + c] = make_float2(tf32r(v00), tf32r(v01));
                *(float2*)&C[(size_t)(r + 8) * DM + c] = make_float2(tf32r(v10), tf32r(v11));
            }
        }
    }
}

// ---------------------------------------------------------------------------
// Flash attention, tf32 mma.sync, causal. BQ=128, BK=64, 256 threads.
// BYTE-IDENTICAL to the round-10/15/16 measured-best kernel. DO NOT TOUCH:
// this schedule is a fragile local optimum (R13/R14 evidence).
// ---------------------------------------------------------------------------
#define KSS 68
#define VSS 72
#define KVSTG 8960                       // floats: 64*68 + 64*72
#define ATT_SMEM (3 * KVSTG * 4)         // 107520 B

__global__ __launch_bounds__(256, 2) void flash_tf32(
    const float* __restrict__ Q, const float* __restrict__ K,
    const float* __restrict__ V, float* __restrict__ O)
{
    extern __shared__ float sm[];
    const int h  = blockIdx.y;
    const int qb = gridDim.x - 1 - blockIdx.x;   // long causal rows first
    const int q0 = qb * 128;
    const int t = threadIdx.x, lane = t & 31, w = t >> 5;
    const int g = lane >> 2, tg = lane & 3;
    const int s1 = (lane & ~3) | (tg >> 1);      // quad-transpose src lanes
    const int s2 = s1 + 2;
    const bool odd = (tg & 1);

    auto issue_kv = [&](int jb, int st) {
        float* Ks = sm + st * KVSTG;
        float* Vs = Ks + 64 * KSS;
        const int k0 = jb * 64;
#pragma unroll
        for (int it = 0; it < 4; it++) {
            int lin = it * 256 + t, r = lin >> 4, c = (lin & 15) << 2;
            CPA16(s2u(&Ks[r * KSS + c]), &K[(size_t)(k0 + r) * DM + h * HD + c]);
            CPA16(s2u(&Vs[r * VSS + c]), &V[(size_t)(k0 + r) * DM + h * HD + c]);
        }
        CPA_COMMIT();
    };

    // groups: [KV0][Q][KV1]
    issue_kv(0, 0);
    {
        float* QB = sm + 2 * KVSTG;
#pragma unroll
        for (int it = 0; it < 8; it++) {
            int lin = it * 256 + t, r = lin >> 4, c = (lin & 15) << 2;
            CPA16(s2u(&QB[r * 68 + c]), &Q[(size_t)(q0 + r) * DM + h * HD + c]);
        }
        CPA_COMMIT();
    }
    issue_kv(1, 1);

    CPA_WAIT1();          // KV0 + Q complete (KV1 may be in flight)
    __syncthreads();

    uint32_t qf[8][4];
    {
        const uint32_t* QB = (const uint32_t*)(sm + 2 * KVSTG);
#pragma unroll
        for (int ks = 0; ks < 8; ks++) {
            int rb = w * 16, kb = ks * 8;
            qf[ks][0] = QB[(rb + g) * 68 + kb + tg];
            qf[ks][1] = QB[(rb + g + 8) * 68 + kb + tg];
            qf[ks][2] = QB[(rb + g) * 68 + kb + tg + 4];
            qf[ks][3] = QB[(rb + g + 8) * 68 + kb + tg + 4];
        }
    }

    float m0r = -1e30f, m1r = -1e30f, l0 = 0.0f, l1 = 0.0f;
    float ao[8][4];
#pragma unroll
    for (int nt = 0; nt < 8; nt++)
#pragma unroll
        for (int c = 0; c < 4; c++) ao[nt][c] = 0.0f;

    const int jbmax = 2 * qb + 1;

    for (int jb = 0; jb <= jbmax; jb++) {
        CPA_WAIT1();          // KV(jb) landed (KV(jb+1) may be in flight)
        __syncthreads();      // visibility + all warps done with stage jb-1
        if (jb + 2 <= jbmax) issue_kv(jb + 2, (jb + 2) % 3);

        const int k0 = jb * 64;
        const int off = k0 - q0;
        // off==64: warps 0-3 (rows < 64) fully masked -> exact skip
        if (off == 64 && w < 4) continue;

        const uint32_t* Ks = (const uint32_t*)(sm + (jb % 3) * KVSTG);
        const uint32_t* Vs = Ks + 64 * KSS;

        // S = Q K^T
        float sc[8][4];
#pragma unroll
        for (int nt = 0; nt < 8; nt++)
#pragma unroll
            for (int c = 0; c < 4; c++) sc[nt][c] = 0.0f;

#pragma unroll
        for (int ks = 0; ks < 8; ks++) {
            const int kb = ks * 8;
#pragma unroll
            for (int nt = 0; nt < 8; nt++) {
                uint32_t b0 = Ks[(nt * 8 + g) * KSS + kb + tg];
                uint32_t b1 = Ks[(nt * 8 + g) * KSS + kb + tg + 4];
                mma8(sc[nt], qf[ks], b0, b1);
            }
        }

        // scale + causal mask
        const float scl = 0.125f;
        if (off >= 0) {
            int lim0 = w * 16 + g - off, lim1 = lim0 + 8;
#pragma unroll
            for (int nt = 0; nt < 8; nt++) {
                int c0 = nt * 8 + 2 * tg, c1 = c0 + 1;
                sc[nt][0] = (c0 <= lim0) ? sc[nt][0] * scl : -1e9f;
                sc[nt][1] = (c1 <= lim0) ? sc[nt][1] * scl : -1e9f;
                sc[nt][2] = (c0 <= lim1) ? sc[nt][2] * scl : -1e9f;
                sc[nt][3] = (c1 <= lim1) ? sc[nt][3] * scl : -1e9f;
            }
        } else {
#pragma unroll
            for (int nt = 0; nt < 8; nt++)
#pragma unroll
                for (int c = 0; c < 4; c++) sc[nt][c] *= scl;
        }

        // online softmax
        float mx0 = -1e30f, mx1 = -1e30f;
#pragma unroll
        for (int nt = 0; nt < 8; nt++) {
            mx0 = fmaxf(mx0, fmaxf(sc[nt][0], sc[nt][1]));
            mx1 = fmaxf(mx1, fmaxf(sc[nt][2], sc[nt][3]));
        }
        mx0 = fmaxf(mx0, __shfl_xor_sync(0xffffffffu, mx0, 1));
        mx0 = fmaxf(mx0, __shfl_xor_sync(0xffffffffu, mx0, 2));
        mx1 = fmaxf(mx1, __shfl_xor_sync(0xffffffffu, mx1, 1));
        mx1 = fmaxf(mx1, __shfl_xor_sync(0xffffffffu, mx1, 2));

        float mn0 = fmaxf(m0r, mx0), mn1 = fmaxf(m1r, mx1);
        float al0 = __expf(m0r - mn0), al1 = __expf(m1r - mn1);
        m0r = mn0; m1r = mn1;

        float rs0 = 0.0f, rs1 = 0.0f;
#pragma unroll
        for (int nt = 0; nt < 8; nt++) {
            sc[nt][0] = __expf(sc[nt][0] - mn0);
            sc[nt][1] = __expf(sc[nt][1] - mn0);
            sc[nt][2] = __expf(sc[nt][2] - mn1);
            sc[nt][3] = __expf(sc[nt][3] - mn1);
            rs0 += sc[nt][0] + sc[nt][1];
            rs1 += sc[nt][2] + sc[nt][3];
        }
        l0 = l0 * al0 + rs0;      // per-lane partial; exact (al uniform in quad)
        l1 = l1 * al1 + rs1;
#pragma unroll
        for (int nt = 0; nt < 8; nt++) {
            ao[nt][0] *= al0; ao[nt][1] *= al0;
            ao[nt][2] *= al1; ao[nt][3] *= al1;
        }

        // O += P V : P C-frag -> A-frag via quad shuffles (no smem)
#pragma unroll
        for (int ks = 0; ks < 8; ks++) {
            const int kb = ks * 8;
            float p0 = tf32r(sc[ks][0]), p1 = tf32r(sc[ks][1]);
            float p2 = tf32r(sc[ks][2]), p3 = tf32r(sc[ks][3]);
            float t00 = __shfl_sync(0xffffffffu, p0, s1);
            float t01 = __shfl_sync(0xffffffffu, p1, s1);
            float t10 = __shfl_sync(0xffffffffu, p2, s1);
            float t11 = __shfl_sync(0xffffffffu, p3, s1);
            float t20 = __shfl_sync(0xffffffffu, p0, s2);
            float t21 = __shfl_sync(0xffffffffu, p1, s2);
            float t30 = __shfl_sync(0xffffffffu, p2, s2);
            float t31 = __shfl_sync(0xffffffffu, p3, s2);
            uint32_t pf[4];
            pf[0] = __float_as_uint(odd ? t01 : t00);   // P[g][kb+tg]
            pf[1] = __float_as_uint(odd ? t11 : t10);   // P[g+8][kb+tg]
            pf[2] = __float_as_uint(odd ? t21 : t20);   // P[g][kb+tg+4]
            pf[3] = __float_as_uint(odd ? t31 : t30);   // P[g+8][kb+tg+4]
#pragma unroll
            for (int nt = 0; nt < 8; nt++) {
                uint32_t b0 = Vs[(kb + tg) * VSS + nt * 8 + g];
                uint32_t b1 = Vs[(kb + tg + 4) * VSS + nt * 8 + g];
                mma8(ao[nt], pf, b0, b1);
            }
        }
    }

    // epilogue: reduce deferred l across the 4-lane group, normalize, store
    l0 += __shfl_xor_sync(0xffffffffu, l0, 1);
    l0 += __shfl_xor_sync(0xffffffffu, l0, 2);
    l1 += __shfl_xor_sync(0xffffffffu, l1, 1);
    l1 += __shfl_xor_sync(0xffffffffu, l1, 2);
    float inv0 = 1.0f / l0, inv1 = 1.0f / l1;
    int r0 = q0 + w * 16 + g, r1 = r0 + 8;
#pragma unroll
    for (int nt = 0; nt < 8; nt++) {
        int c = nt * 8 + 2 * tg;
        *(float2*)&O[(size_t)r0 * DM + h * HD + c] =
            make_float2(tf32r(ao[nt][0] * inv0), tf32r(ao[nt][1] * inv0));
        *(float2*)&O[(size_t)r1 * DM + h * HD + c] =
            make_float2(tf32r(ao[nt][2] * inv1), tf32r(ao[nt][3] * inv1));
    }
}

// ---------------------------------------------------------------------------
// Launch
// ---------------------------------------------------------------------------
extern "C" void kernel_launch(void* const* d_in, const int* in_sizes, int n_in,
                              void* d_out, int out_size)
{
    (void)in_sizes; (void)n_in; (void)out_size;
    const float* x  = (const float*)d_in[0];
    const float* Wq = (const float*)d_in[2];
    const float* Wk = (const float*)d_in[3];
    const float* Wv = (const float*)d_in[4];
    const float* Wo = (const float*)d_in[5];
    const float* bo = (const float*)d_in[6];
    float* out = (float*)d_out;

    float *Qp, *Kp, *Vp, *AO;
    cudaGetSymbolAddress((void**)&Qp, g_Q);
    cudaGetSymbolAddress((void**)&Kp, g_K);
    cudaGetSymbolAddress((void**)&Vp, g_V);
    cudaGetSymbolAddress((void**)&AO, g_AO);

    cudaFuncSetAttribute(flash_tf32,
                         cudaFuncAttributeMaxDynamicSharedMemorySize, ATT_SMEM);
    cudaFuncSetAttribute((const void*)gemm_tf32<false, 4>,
                         cudaFuncAttributeMaxDynamicSharedMemorySize, GEMM_SMEM);
    cudaFuncSetAttribute((const void*)gemm_tf32<true, 2>,
                         cudaFuncAttributeMaxDynamicSharedMemorySize, GEMM_SMEM);

    // RoPE tables (must precede the QKV GEMM epilogue)
    invfreq_kernel<<<1, 32>>>();
    rope_table_kernel<<<(SEQ * 32) / 256, 256>>>();

    // Fused QKV projection + RoPE + tf32 pre-round (128-row tiles, 576 CTAs)
    gemm_tf32<false, 4><<<dim3(18, 32), 256, GEMM_SMEM>>>(
        x, Wq, Wk, Wv, nullptr, Qp, Kp, Vp);

    flash_tf32<<<dim3(SEQ / 128, NH), 256, ATT_SMEM>>>(Qp, Kp, Vp, AO);

    // Output projection + bias (64-row tiles -> 384 CTAs, full wave packing)
    gemm_tf32<true, 2><<<dim3(6, 64), 256, GEMM_SMEM>>>(
        AO, Wo, Wo, Wo, bo, out, out, out);
}